// round 12
// baseline (speedup 1.0000x reference)
#include <cuda_runtime.h>
#include <cuda_fp16.h>
#include <math.h>
#include <stdint.h>

#define B_    2
#define T_    2048
#define D_    1024
#define HV_   16
#define HK_   8
#define KDIM_ 512
#define VDIM_ 1024
#define CONVD 2048
#define MIXW  3072          // mixed buffer width: [qkv 2048 | z 1024]
#define EPS_  1e-6f
#define NTOK  (B_*T_)       // 4096
#define THALF (T_/2)

// ======================= PTX helpers ======================================
__device__ __forceinline__ uint32_t smem_to_u32(const void* p) {
    uint32_t a;
    asm("{ .reg .u64 t; cvta.to.shared.u64 t, %1; cvt.u32.u64 %0, t; }" : "=r"(a) : "l"(p));
    return a;
}
__device__ __forceinline__ void ldsm_x4(uint32_t* r, uint32_t addr) {
    asm volatile("ldmatrix.sync.aligned.m8n8.x4.shared.b16 {%0,%1,%2,%3}, [%4];"
        : "=r"(r[0]), "=r"(r[1]), "=r"(r[2]), "=r"(r[3]) : "r"(addr));
}
__device__ __forceinline__ void mma16816f(float* c, const uint32_t* a, const uint32_t* b) {
    asm volatile("mma.sync.aligned.m16n8k16.row.col.f32.f16.f16.f32 "
        "{%0,%1,%2,%3}, {%4,%5,%6,%7}, {%8,%9}, {%0,%1,%2,%3};"
        : "+f"(c[0]), "+f"(c[1]), "+f"(c[2]), "+f"(c[3])
        : "r"(a[0]), "r"(a[1]), "r"(a[2]), "r"(a[3]), "r"(b[0]), "r"(b[1]));
}
#define CP16(sm, gp) asm volatile("cp.async.cg.shared.global [%0], [%1], 16;" :: "r"(sm), "l"(gp))
#define CP_COMMIT()  asm volatile("cp.async.commit_group;" ::: "memory")
#define CP_WAIT1()   asm volatile("cp.async.wait_group 1;" ::: "memory")
#define CP_WAIT0()   asm volatile("cp.async.wait_group 0;" ::: "memory")

// byte offset of (row, kc) 16B-unit in a [128 x 32fp16] tile, xor-swizzled
__device__ __forceinline__ uint32_t tunit(int row, int kc) {
    return (uint32_t)((row*4 + (kc ^ ((row >> 1) & 3))) * 16);
}

// ======================= static scratch ===================================
__device__ float g_mixed[NTOK*MIXW];        // [qkv | z]
__device__ float g_beta[NTOK*HV_];
__device__ float g_gg[NTOK*HV_];
__device__ float g_qn[NTOK*HK_*64];
__device__ float g_kn[NTOK*HK_*64];
__device__ float g_v[NTOK*VDIM_];
__device__ float g_o[NTOK*VDIM_];
__device__ __half g_hid[NTOK*D_];
__device__ __half g_w1h[MIXW*D_], g_w1l[MIXW*D_];     // [N=3072,K] hi/lo
__device__ __half g_woh[D_*VDIM_], g_wol[D_*VDIM_];   // [N=1024,K] hi/lo
__device__ __half g_onh[NTOK*VDIM_], g_onl[NTOK*VDIM_];
// recurrence carried state between chunks (512 warps x 32 lanes)
__device__ float g_Sst[512*32*8];
__device__ float g_kst[512*32*8];
__device__ float g_dst[512*32];

// ======================= fp32 -> fp16 (elementwise) =======================
__global__ __launch_bounds__(256) void cvt_f2h(const float* __restrict__ src,
        __half* __restrict__ dst, int n4)
{
    int i = blockIdx.x*256 + threadIdx.x;
    if (i >= n4) return;
    float4 x = ((const float4*)src)[i];
    ((__half2*)dst)[2*i]   = __floats2half2_rn(x.x, x.y);
    ((__half2*)dst)[2*i+1] = __floats2half2_rn(x.z, x.w);
}

// ===== transpose + convert: W[K,N] fp32 -> Wt[N,K] fp16 hi/lo =============
__global__ __launch_bounds__(256) void tconv_f2h2(const float* __restrict__ W,
        __half* __restrict__ Wh, __half* __restrict__ Wl, int K, int N)
{
    __shared__ float tile[32][33];
    int n0 = blockIdx.x*32, k0 = blockIdx.y*32;
    int tx = threadIdx.x, ty = threadIdx.y;   // 32 x 8
    #pragma unroll
    for (int j = 0; j < 32; j += 8)
        tile[ty+j][tx] = W[(long)(k0+ty+j)*N + n0 + tx];
    __syncthreads();
    #pragma unroll
    for (int j = 0; j < 32; j += 8) {
        float x = tile[tx][ty+j];
        __half h = __float2half(x);
        long o = (long)(n0+ty+j)*K + k0 + tx;
        Wh[o] = h;
        Wl[o] = __float2half(x - __half2float(h));
    }
}

// =============== GEMM variant 1: A fp16, W split hi/lo (2 MMA) ===========
#define STG2 24576   // A 8K | Bh 8K | Bl 8K
__global__ __launch_bounds__(256) void gemm_w2(
    const __half* __restrict__ A, const __half* __restrict__ Bh,
    const __half* __restrict__ Bl, float* __restrict__ C, int M, int N, int K)
{
    extern __shared__ __align__(128) char smem[];
    uint32_t sb = smem_to_u32(smem);
    int tid = threadIdx.x, lane = tid & 31, wid = tid >> 5;
    int wm = wid & 3, wn = wid >> 2;
    int bx = blockIdx.x, by = blockIdx.y;
    const int NC = K >> 5;

    float acc[2][8][4];
    #pragma unroll
    for (int i = 0; i < 2; i++)
        #pragma unroll
        for (int j = 0; j < 8; j++)
            #pragma unroll
            for (int q = 0; q < 4; q++) acc[i][j][q] = 0.f;

    #define LOAD_W2(ic, s) do { \
        long kof = (long)(ic) * 32; \
        uint32_t st = sb + (s)*STG2; \
        _Pragma("unroll") \
        for (int j = 0; j < 2; j++) { \
            int u = tid + j*256; int row = u >> 2, kc = u & 3; \
            uint32_t sw = tunit(row, kc); \
            long ao = (long)(by*128 + row)*K + kof + kc*8; \
            long bo = (long)(bx*128 + row)*K + kof + kc*8; \
            CP16(st + sw,          A  + ao); \
            CP16(st + 8192 + sw,   Bh + bo); \
            CP16(st + 16384 + sw,  Bl + bo); \
        } \
        CP_COMMIT(); \
    } while (0)

    LOAD_W2(0, 0);
    LOAD_W2(1, 1);

    int lr = lane & 15, lk = lane >> 4;
    for (int ic = 0; ic < NC; ic++) {
        int s = ic - (ic/3)*3;
        if (ic + 1 < NC) CP_WAIT1(); else CP_WAIT0();
        __syncthreads();
        if (ic + 2 < NC) { int s2 = (ic+2) - ((ic+2)/3)*3; LOAD_W2(ic + 2, s2); }

        uint32_t pA = sb + s*STG2, pBh = pA + 8192, pBl = pA + 16384;
        #pragma unroll
        for (int ks = 0; ks < 2; ks++) {
            uint32_t a[2][4], bh[8][2], bl[8][2];
            #pragma unroll
            for (int mt = 0; mt < 2; mt++)
                ldsm_x4(a[mt], pA + tunit(wm*32 + mt*16 + lr, ks*2 + lk));
            #pragma unroll
            for (int bp = 0; bp < 4; bp++) {
                uint32_t off = tunit(wn*64 + bp*16 + lr, ks*2 + lk);
                uint32_t t[4];
                ldsm_x4(t, pBh + off);
                bh[bp*2][0]=t[0]; bh[bp*2][1]=t[2]; bh[bp*2+1][0]=t[1]; bh[bp*2+1][1]=t[3];
                ldsm_x4(t, pBl + off);
                bl[bp*2][0]=t[0]; bl[bp*2][1]=t[2]; bl[bp*2+1][0]=t[1]; bl[bp*2+1][1]=t[3];
            }
            #pragma unroll
            for (int mt = 0; mt < 2; mt++)
                #pragma unroll
                for (int nt = 0; nt < 8; nt++) {
                    mma16816f(acc[mt][nt], a[mt], bh[nt]);
                    mma16816f(acc[mt][nt], a[mt], bl[nt]);
                }
        }
    }

    #pragma unroll
    for (int mt = 0; mt < 2; mt++)
        #pragma unroll
        for (int nt = 0; nt < 8; nt++) {
            long r = by*128 + wm*32 + mt*16 + (lane >> 2);
            long c = bx*128 + wn*64 + nt*8 + (lane & 3)*2;
            *(float2*)&C[r*N + c]     = make_float2(acc[mt][nt][0], acc[mt][nt][1]);
            *(float2*)&C[(r+8)*N + c] = make_float2(acc[mt][nt][2], acc[mt][nt][3]);
        }
}

// ====== GEMM variant 2: A+W split (3 MMA), with row offset for M-slices ===
#define STG3 32768   // Ah 8K | Al 8K | Bh 8K | Bl 8K
__global__ __launch_bounds__(256) void gemm_f3(
    const __half* __restrict__ Ah, const __half* __restrict__ Al,
    const __half* __restrict__ Bh, const __half* __restrict__ Bl,
    float* __restrict__ C, int row0, int N, int K)
{
    extern __shared__ __align__(128) char smem[];
    uint32_t sb = smem_to_u32(smem);
    int tid = threadIdx.x, lane = tid & 31, wid = tid >> 5;
    int wm = wid & 3, wn = wid >> 2;
    int bx = blockIdx.x, by = blockIdx.y;
    const int NC = K >> 5;

    float acc[2][8][4];
    #pragma unroll
    for (int i = 0; i < 2; i++)
        #pragma unroll
        for (int j = 0; j < 8; j++)
            #pragma unroll
            for (int q = 0; q < 4; q++) acc[i][j][q] = 0.f;

    #define LOAD_F3(ic, s) do { \
        long kof = (long)(ic) * 32; \
        uint32_t st = sb + (s)*STG3; \
        _Pragma("unroll") \
        for (int j = 0; j < 2; j++) { \
            int u = tid + j*256; int row = u >> 2, kc = u & 3; \
            uint32_t sw = tunit(row, kc); \
            long ao = (long)(row0 + by*128 + row)*K + kof + kc*8; \
            long bo = (long)(bx*128 + row)*K + kof + kc*8; \
            CP16(st + sw,          Ah + ao); \
            CP16(st + 8192 + sw,   Al + ao); \
            CP16(st + 16384 + sw,  Bh + bo); \
            CP16(st + 24576 + sw,  Bl + bo); \
        } \
        CP_COMMIT(); \
    } while (0)

    LOAD_F3(0, 0);
    LOAD_F3(1, 1);

    int lr = lane & 15, lk = lane >> 4;
    for (int ic = 0; ic < NC; ic++) {
        int s = ic - (ic/3)*3;
        if (ic + 1 < NC) CP_WAIT1(); else CP_WAIT0();
        __syncthreads();
        if (ic + 2 < NC) { int s2 = (ic+2) - ((ic+2)/3)*3; LOAD_F3(ic + 2, s2); }

        uint32_t pAh = sb + s*STG3, pAl = pAh + 8192;
        uint32_t pBh = pAh + 16384, pBl = pAh + 24576;
        #pragma unroll
        for (int ks = 0; ks < 2; ks++) {
            uint32_t ah[2][4], al[2][4], bh[8][2], bl[8][2];
            #pragma unroll
            for (int mt = 0; mt < 2; mt++) {
                uint32_t off = tunit(wm*32 + mt*16 + lr, ks*2 + lk);
                ldsm_x4(ah[mt], pAh + off);
                ldsm_x4(al[mt], pAl + off);
            }
            #pragma unroll
            for (int bp = 0; bp < 4; bp++) {
                uint32_t off = tunit(wn*64 + bp*16 + lr, ks*2 + lk);
                uint32_t t[4];
                ldsm_x4(t, pBh + off);
                bh[bp*2][0]=t[0]; bh[bp*2][1]=t[2]; bh[bp*2+1][0]=t[1]; bh[bp*2+1][1]=t[3];
                ldsm_x4(t, pBl + off);
                bl[bp*2][0]=t[0]; bl[bp*2][1]=t[2]; bl[bp*2+1][0]=t[1]; bl[bp*2+1][1]=t[3];
            }
            #pragma unroll
            for (int mt = 0; mt < 2; mt++)
                #pragma unroll
                for (int nt = 0; nt < 8; nt++) {
                    mma16816f(acc[mt][nt], ah[mt], bh[nt]);
                    mma16816f(acc[mt][nt], ah[mt], bl[nt]);
                    mma16816f(acc[mt][nt], al[mt], bh[nt]);
                }
        }
    }

    #pragma unroll
    for (int mt = 0; mt < 2; mt++)
        #pragma unroll
        for (int nt = 0; nt < 8; nt++) {
            long r = row0 + by*128 + wm*32 + mt*16 + (lane >> 2);
            long c = bx*128 + wn*64 + nt*8 + (lane & 3)*2;
            *(float2*)&C[r*N + c]     = make_float2(acc[mt][nt][0], acc[mt][nt][1]);
            *(float2*)&C[(r+8)*N + c] = make_float2(acc[mt][nt][2], acc[mt][nt][3]);
        }
}

// ======================= beta / g projections =============================
__global__ __launch_bounds__(256) void betag_kernel(
    const float* __restrict__ hid, const float* __restrict__ Wb,
    const float* __restrict__ Wa, const float* __restrict__ dtb,
    const float* __restrict__ Alog)
{
    int row = blockIdx.x;
    int tid = threadIdx.x;
    __shared__ float sh[D_];
    __shared__ float red[256];
    *(float4*)&sh[tid*4] = *(const float4*)(hid + (long)row*D_ + tid*4);
    __syncthreads();
    int c  = tid & 31, sg = tid >> 5;
    const float* W = (c < 16) ? Wb : Wa;
    int cc = c & 15, k0 = sg * 128;
    float acc = 0.f;
    #pragma unroll 8
    for (int k = 0; k < 128; k++)
        acc = fmaf(sh[k0 + k], W[(k0 + k)*HV_ + cc], acc);
    red[tid] = acc;
    __syncthreads();
    if (tid < 32) {
        float s = 0.f;
        #pragma unroll
        for (int si = 0; si < 8; si++) s += red[si*32 + c];
        if (c < 16) g_beta[(long)row*HV_ + cc] = 1.f / (1.f + expf(-s));
        else {
            float x  = s + dtb[cc];
            float sp = (x > 20.f) ? x : log1pf(expf(x));
            g_gg[(long)row*HV_ + cc] = -expf(Alog[cc]) * sp;
        }
    }
}

// ============== causal conv + SiLU + split + l2norm =======================
__global__ __launch_bounds__(256) void conv_kernel(const float* __restrict__ convw)
{
    int t = blockIdx.x, b = blockIdx.y;
    int tid = threadIdx.x;
    long row = (long)(b*T_ + t);
    __shared__ float sy[CONVD];
    #pragma unroll
    for (int j = 0; j < 8; j++) {
        int c = tid + j*256;
        float4 w = *(const float4*)(convw + c*4);
        float acc = g_mixed[row*MIXW + c] * w.w;
        if (t >= 1) acc = fmaf(g_mixed[(row-1)*MIXW + c], w.z, acc);
        if (t >= 2) acc = fmaf(g_mixed[(row-2)*MIXW + c], w.y, acc);
        if (t >= 3) acc = fmaf(g_mixed[(row-3)*MIXW + c], w.x, acc);
        sy[c] = acc / (1.f + __expf(-acc));
    }
    __syncthreads();
    int wrp = tid >> 5, lane = tid & 31;
    {
        float y0 = sy[wrp*64 + lane], y1 = sy[wrp*64 + 32 + lane];
        float ss = y0*y0 + y1*y1;
        #pragma unroll
        for (int off = 16; off; off >>= 1) ss += __shfl_xor_sync(0xffffffffu, ss, off);
        float rs = rsqrtf(ss + EPS_) * 0.125f;
        g_qn[(row*HK_ + wrp)*64 + lane]      = y0 * rs;
        g_qn[(row*HK_ + wrp)*64 + 32 + lane] = y1 * rs;
    }
    {
        float y0 = sy[KDIM_ + wrp*64 + lane], y1 = sy[KDIM_ + wrp*64 + 32 + lane];
        float ss = y0*y0 + y1*y1;
        #pragma unroll
        for (int off = 16; off; off >>= 1) ss += __shfl_xor_sync(0xffffffffu, ss, off);
        float rs = rsqrtf(ss + EPS_);
        g_kn[(row*HK_ + wrp)*64 + lane]      = y0 * rs;
        g_kn[(row*HK_ + wrp)*64 + 32 + lane] = y1 * rs;
    }
    #pragma unroll
    for (int j = 0; j < 4; j++) {
        int c = tid + j*256;
        g_v[row*VDIM_ + c] = sy[1024 + c];
    }
}

// ======= gated delta recurrence: R7 inner loop, chunked over t ============
#define PF 4
__global__ __launch_bounds__(128) void recurrence_kernel(int tbeg, int tend)
{
    int w = blockIdx.x*4 + (threadIdx.x >> 5);    // 0..511
    int lane = threadIdx.x & 31;
    int bh = w >> 4, cg = w & 15;
    int b = bh >> 4, h = bh & 15, kh = h >> 1;
    int colIdx = lane >> 3, rseg = lane & 7;
    int col = cg*4 + colIdx;

    const float* kb = g_kn   + ((long)(b*T_)*HK_ + kh)*64 + rseg*8;
    const float* qb = g_qn   + ((long)(b*T_)*HK_ + kh)*64 + rseg*8;
    const float* vb = g_v    + ((long)(b*T_)*HV_ + h)*64 + col;
    const float* gb = g_gg   + (long)(b*T_)*HV_ + h;
    const float* bb = g_beta + (long)(b*T_)*HV_ + h;
    float*       ob = g_o    + ((long)(b*T_)*HV_ + h)*64 + col;
    const long qs = (long)HK_*64, vs = (long)HV_*64, gs = HV_;
    long stbase = ((long)w*32 + lane)*8;

    float S[8], kprev[8], dprev;
    if (tbeg == 0) {
        dprev = 0.f;
        #pragma unroll
        for (int i = 0; i < 8; i++) { S[i] = 0.f; kprev[i] = 0.f; }
    } else {
        dprev = g_dst[(long)w*32 + lane];
        #pragma unroll
        for (int i = 0; i < 8; i++) { S[i] = g_Sst[stbase+i]; kprev[i] = g_kst[stbase+i]; }
    }

    float4 pk0[PF], pk1[PF], pq0[PF], pq1[PF];
    float  pv[PF], pg[PF], pb[PF];
    #pragma unroll
    for (int j = 0; j < PF; j++) {
        long o = tbeg + j;
        pk0[j] = *(const float4*)(kb + o*qs);  pk1[j] = *(const float4*)(kb + o*qs + 4);
        pq0[j] = *(const float4*)(qb + o*qs);  pq1[j] = *(const float4*)(qb + o*qs + 4);
        pv[j] = vb[o*vs];  pg[j] = gb[o*gs];  pb[j] = bb[o*gs];
    }

    for (int t0 = tbeg; t0 < tend; t0 += PF) {
        #pragma unroll
        for (int j = 0; j < PF; j++) {
            int t = t0 + j;
            float4 k0 = pk0[j], k1 = pk1[j], q0 = pq0[j], q1 = pq1[j];
            float vv = pv[j], gv = pg[j], bv = pb[j];
            if (t + PF < T_) {                      // stays in-bounds across chunks
                long o = (long)(t + PF);
                pk0[j] = *(const float4*)(kb + o*qs);  pk1[j] = *(const float4*)(kb + o*qs + 4);
                pq0[j] = *(const float4*)(qb + o*qs);  pq1[j] = *(const float4*)(qb + o*qs + 4);
                pv[j] = vb[o*vs];  pg[j] = gb[o*gs];  pb[j] = bb[o*gs];
            }

            float eg = __expf(gv);
            float kc[8] = {k0.x,k0.y,k0.z,k0.w,k1.x,k1.y,k1.z,k1.w};
            float qc[8] = {q0.x,q0.y,q0.z,q0.w,q1.x,q1.y,q1.z,q1.w};
            float kva = 0.f, kvb2 = 0.f, oa = 0.f, ob2 = 0.f, qa = 0.f, qb2 = 0.f;
            #pragma unroll
            for (int i = 0; i < 4; i++) {
                S[i] = fmaf(kprev[i], dprev, S[i]) * eg;
                kva = fmaf(kc[i], S[i], kva);
                oa  = fmaf(qc[i], S[i], oa);
                qa  = fmaf(qc[i], kc[i], qa);
                kprev[i] = kc[i];
            }
            #pragma unroll
            for (int i = 4; i < 8; i++) {
                S[i] = fmaf(kprev[i], dprev, S[i]) * eg;
                kvb2 = fmaf(kc[i], S[i], kvb2);
                ob2  = fmaf(qc[i], S[i], ob2);
                qb2  = fmaf(qc[i], kc[i], qb2);
                kprev[i] = kc[i];
            }
            float kvp = kva + kvb2, op = oa + ob2, qkp = qa + qb2;
            #pragma unroll
            for (int off = 1; off < 8; off <<= 1) {
                kvp += __shfl_xor_sync(0xffffffffu, kvp, off);
                op  += __shfl_xor_sync(0xffffffffu, op,  off);
                qkp += __shfl_xor_sync(0xffffffffu, qkp, off);
            }
            float delta = (vv - kvp) * bv;
            if (rseg == 0) ob[(long)t*vs] = fmaf(qkp, delta, op);
            dprev = delta;
        }
    }

    if (tend < T_) {
        g_dst[(long)w*32 + lane] = dprev;
        #pragma unroll
        for (int i = 0; i < 8; i++) { g_Sst[stbase+i] = S[i]; g_kst[stbase+i] = kprev[i]; }
    }
}

// ========== gated RMSNorm * silu(z), fp16 hi/lo out, t-range ==============
__global__ __launch_bounds__(256) void gnorm_kernel(const float* __restrict__ nw, int toff)
{
    int t = blockIdx.x + toff, b = blockIdx.y;
    long row = (long)(b*T_ + t);
    int wrp = threadIdx.x >> 5, lane = threadIdx.x & 31;
    #pragma unroll
    for (int hh = wrp; hh < HV_; hh += 8) {
        float o0 = g_o[(row*HV_ + hh)*64 + lane];
        float o1 = g_o[(row*HV_ + hh)*64 + 32 + lane];
        float ss = o0*o0 + o1*o1;
        #pragma unroll
        for (int off = 16; off; off >>= 1) ss += __shfl_xor_sync(0xffffffffu, ss, off);
        float rs = rsqrtf(ss * (1.f/64.f) + EPS_);
        float z0 = g_mixed[row*MIXW + CONVD + hh*64 + lane];
        float z1 = g_mixed[row*MIXW + CONVD + hh*64 + 32 + lane];
        float v0 = o0 * rs * nw[lane]      * (z0 / (1.f + __expf(-z0)));
        float v1 = o1 * rs * nw[lane + 32] * (z1 / (1.f + __expf(-z1)));
        long i0 = row*VDIM_ + hh*64 + lane;
        __half h0 = __float2half(v0), h1 = __float2half(v1);
        g_onh[i0]      = h0;
        g_onh[i0 + 32] = h1;
        g_onl[i0]      = __float2half(v0 - __half2float(h0));
        g_onl[i0 + 32] = __float2half(v1 - __half2float(h1));
    }
}

// ==========================================================================
extern "C" void kernel_launch(void* const* d_in, const int* in_sizes, int n_in,
                              void* d_out, int out_size)
{
    (void)in_sizes; (void)n_in; (void)out_size;
    const float* hid   = (const float*)d_in[0];
    const float* Wqkv  = (const float*)d_in[1];
    const float* Wz    = (const float*)d_in[2];
    const float* Wb    = (const float*)d_in[3];
    const float* Wa    = (const float*)d_in[4];
    const float* dtb   = (const float*)d_in[5];
    const float* Alog  = (const float*)d_in[6];
    const float* convw = (const float*)d_in[7];
    const float* nw    = (const float*)d_in[8];
    const float* Wout  = (const float*)d_in[9];
    float* out = (float*)d_out;

    float *mixed;
    __half *hh, *w1h, *w1l, *woh, *wol, *onh, *onl;
    cudaGetSymbolAddress((void**)&mixed, g_mixed);
    cudaGetSymbolAddress((void**)&hh,  g_hid);
    cudaGetSymbolAddress((void**)&w1h, g_w1h);  cudaGetSymbolAddress((void**)&w1l, g_w1l);
    cudaGetSymbolAddress((void**)&woh, g_woh);  cudaGetSymbolAddress((void**)&wol, g_wol);
    cudaGetSymbolAddress((void**)&onh, g_onh);  cudaGetSymbolAddress((void**)&onl, g_onl);

    static int init_done = 0;
    static cudaStream_t s1;
    static cudaEvent_t evCvt, evBetag, evQkv, evZ, evRec1, evSideDone;
    if (!init_done) {
        cudaFuncSetAttribute(gemm_w2, cudaFuncAttributeMaxDynamicSharedMemorySize, 3*STG2);
        cudaFuncSetAttribute(gemm_f3, cudaFuncAttributeMaxDynamicSharedMemorySize, 3*STG3);
        cudaStreamCreateWithFlags(&s1, cudaStreamNonBlocking);
        cudaEventCreateWithFlags(&evCvt,     cudaEventDisableTiming);
        cudaEventCreateWithFlags(&evBetag,   cudaEventDisableTiming);
        cudaEventCreateWithFlags(&evQkv,     cudaEventDisableTiming);
        cudaEventCreateWithFlags(&evZ,       cudaEventDisableTiming);
        cudaEventCreateWithFlags(&evRec1,    cudaEventDisableTiming);
        cudaEventCreateWithFlags(&evSideDone,cudaEventDisableTiming);
        init_done = 1;
    }

    dim3 g3grid(D_/128, THALF/128);   // (8, 8) per 1024-row slice

    // ---- main stream (0): critical path --------------------------------
    cvt_f2h<<<(NTOK*D_/4 + 255)/256, 256>>>(hid, hh, NTOK*D_/4);
    cudaEventRecord(evCvt, 0);

    // ---- side stream: prep work overlapping GEMM1-qkv ------------------
    cudaStreamWaitEvent(s1, evCvt, 0);
    betag_kernel<<<NTOK, 256, 0, s1>>>(hid, Wb, Wa, dtb, Alog);
    cudaEventRecord(evBetag, s1);
    tconv_f2h2<<<dim3(VDIM_/32, D_/32), dim3(32,8), 0, s1>>>(
        Wz, w1h + (long)CONVD*D_, w1l + (long)CONVD*D_, D_, VDIM_);
    tconv_f2h2<<<dim3(D_/32, VDIM_/32), dim3(32,8), 0, s1>>>(Wout, woh, wol, VDIM_, D_);

    // ---- main: qkv GEMM -> conv -> recurrence chunk 1 -------------------
    tconv_f2h2<<<dim3(CONVD/32, D_/32), dim3(32,8)>>>(Wqkv, w1h, w1l, D_, CONVD);
    gemm_w2<<<dim3(CONVD/128, NTOK/128), 256, 3*STG2>>>(hh, w1h, w1l, mixed, NTOK, MIXW, D_);
    cudaEventRecord(evQkv, 0);
    conv_kernel<<<dim3(T_, B_), 256>>>(convw);
    cudaStreamWaitEvent(0, evBetag, 0);
    recurrence_kernel<<<128, 128>>>(0, THALF);
    cudaEventRecord(evRec1, 0);
    // chunk 2 runs while the side stream does gnorm/GEMM3 for half 1
    recurrence_kernel<<<128, 128>>>(THALF, T_);

    // ---- side: z GEMM into the conv/rec1 window, then half-1 epilogue ---
    cudaStreamWaitEvent(s1, evQkv, 0);
    gemm_w2<<<dim3(VDIM_/128, NTOK/128), 256, 3*STG2, s1>>>(
        hh, w1h + (long)CONVD*D_, w1l + (long)CONVD*D_, mixed + CONVD, NTOK, MIXW, D_);
    cudaEventRecord(evZ, s1);
    cudaStreamWaitEvent(s1, evRec1, 0);
    gnorm_kernel<<<dim3(THALF, B_), 256, 0, s1>>>(nw, 0);
    gemm_f3<<<g3grid, 256, 3*STG3, s1>>>(onh, onl, woh, wol, out, 0,     D_, VDIM_);
    gemm_f3<<<g3grid, 256, 3*STG3, s1>>>(onh, onl, woh, wol, out, 2048,  D_, VDIM_);
    cudaEventRecord(evSideDone, s1);

    // ---- main: half-2 epilogue, then join side stream -------------------
    cudaStreamWaitEvent(0, evZ, 0);
    gnorm_kernel<<<dim3(THALF, B_), 256>>>(nw, THALF);
    gemm_f3<<<g3grid, 256, 3*STG3>>>(onh, onl, woh, wol, out, 1024, D_, VDIM_);
    gemm_f3<<<g3grid, 256, 3*STG3>>>(onh, onl, woh, wol, out, 3072, D_, VDIM_);
    cudaStreamWaitEvent(0, evSideDone, 0);
}

// round 13
// speedup vs baseline: 1.1185x; 1.1185x over previous
#include <cuda_runtime.h>
#include <cuda_fp16.h>
#include <math.h>
#include <stdint.h>

#define B_    2
#define T_    2048
#define D_    1024
#define HV_   16
#define HK_   8
#define KDIM_ 512
#define VDIM_ 1024
#define CONVD 2048
#define MIXW  3072          // fused GEMM width: [qkv 2048 | z 1024]
#define EPS_  1e-6f
#define NTOK  (B_*T_)       // 4096

// ======================= PTX helpers ======================================
__device__ __forceinline__ uint32_t smem_to_u32(const void* p) {
    uint32_t a;
    asm("{ .reg .u64 t; cvta.to.shared.u64 t, %1; cvt.u32.u64 %0, t; }" : "=r"(a) : "l"(p));
    return a;
}
__device__ __forceinline__ void ldsm_x4(uint32_t* r, uint32_t addr) {
    asm volatile("ldmatrix.sync.aligned.m8n8.x4.shared.b16 {%0,%1,%2,%3}, [%4];"
        : "=r"(r[0]), "=r"(r[1]), "=r"(r[2]), "=r"(r[3]) : "r"(addr));
}
__device__ __forceinline__ void mma16816f(float* c, const uint32_t* a, const uint32_t* b) {
    asm volatile("mma.sync.aligned.m16n8k16.row.col.f32.f16.f16.f32 "
        "{%0,%1,%2,%3}, {%4,%5,%6,%7}, {%8,%9}, {%0,%1,%2,%3};"
        : "+f"(c[0]), "+f"(c[1]), "+f"(c[2]), "+f"(c[3])
        : "r"(a[0]), "r"(a[1]), "r"(a[2]), "r"(a[3]), "r"(b[0]), "r"(b[1]));
}
#define CP16(sm, gp) asm volatile("cp.async.cg.shared.global [%0], [%1], 16;" :: "r"(sm), "l"(gp))
#define CP_COMMIT()  asm volatile("cp.async.commit_group;" ::: "memory")
#define CP_WAIT1()   asm volatile("cp.async.wait_group 1;" ::: "memory")
#define CP_WAIT0()   asm volatile("cp.async.wait_group 0;" ::: "memory")

// byte offset of (row, kc) 16B-unit in a [128 x 32fp16] tile, xor-swizzled
__device__ __forceinline__ uint32_t tunit(int row, int kc) {
    return (uint32_t)((row*4 + (kc ^ ((row >> 1) & 3))) * 16);
}

// ======================= static scratch ===================================
__device__ float g_mixed[NTOK*MIXW];        // [qkv | z]
__device__ float g_beta[NTOK*HV_];
__device__ float g_gg[NTOK*HV_];
__device__ float g_qn[NTOK*HK_*64];
__device__ float g_kn[NTOK*HK_*64];
__device__ float g_v[NTOK*VDIM_];
__device__ float g_o[NTOK*VDIM_];
__device__ __half g_hid[NTOK*D_];
__device__ __half g_w1h[MIXW*D_], g_w1l[MIXW*D_];     // [N=3072,K] hi/lo
__device__ __half g_woh[D_*VDIM_], g_wol[D_*VDIM_];   // [N=1024,K] hi/lo
__device__ __half g_onh[NTOK*VDIM_], g_onl[NTOK*VDIM_];

// ======================= fp32 -> fp16 (elementwise) =======================
__global__ __launch_bounds__(256) void cvt_f2h(const float* __restrict__ src,
        __half* __restrict__ dst, int n4)
{
    int i = blockIdx.x*256 + threadIdx.x;
    if (i >= n4) return;
    float4 x = ((const float4*)src)[i];
    ((__half2*)dst)[2*i]   = __floats2half2_rn(x.x, x.y);
    ((__half2*)dst)[2*i+1] = __floats2half2_rn(x.z, x.w);
}

// ===== transpose + convert: W[K,N] fp32 -> Wt[N,K] fp16 hi/lo =============
__global__ __launch_bounds__(256) void tconv_f2h2(const float* __restrict__ W,
        __half* __restrict__ Wh, __half* __restrict__ Wl, int K, int N)
{
    __shared__ float tile[32][33];
    int n0 = blockIdx.x*32, k0 = blockIdx.y*32;
    int tx = threadIdx.x, ty = threadIdx.y;   // 32 x 8
    #pragma unroll
    for (int j = 0; j < 32; j += 8)
        tile[ty+j][tx] = W[(long)(k0+ty+j)*N + n0 + tx];
    __syncthreads();
    #pragma unroll
    for (int j = 0; j < 32; j += 8) {
        float x = tile[tx][ty+j];
        __half h = __float2half(x);
        long o = (long)(n0+ty+j)*K + k0 + tx;
        Wh[o] = h;
        Wl[o] = __float2half(x - __half2float(h));
    }
}

// =============== GEMM variant 1: A fp16, W split hi/lo (2 MMA) ===========
#define STG2 24576   // A 8K | Bh 8K | Bl 8K
__global__ __launch_bounds__(256, 2) void gemm_w2(
    const __half* __restrict__ A, const __half* __restrict__ Bh,
    const __half* __restrict__ Bl, float* __restrict__ C, int M, int N, int K)
{
    extern __shared__ __align__(128) char smem[];
    uint32_t sb = smem_to_u32(smem);
    int tid = threadIdx.x, lane = tid & 31, wid = tid >> 5;
    int wm = wid & 3, wn = wid >> 2;
    int bx = blockIdx.x, by = blockIdx.y;
    const int NC = K >> 5;

    float acc[2][8][4];
    #pragma unroll
    for (int i = 0; i < 2; i++)
        #pragma unroll
        for (int j = 0; j < 8; j++)
            #pragma unroll
            for (int q = 0; q < 4; q++) acc[i][j][q] = 0.f;

    #define LOAD_W2(ic, s) do { \
        long kof = (long)(ic) * 32; \
        uint32_t st = sb + (s)*STG2; \
        _Pragma("unroll") \
        for (int j = 0; j < 2; j++) { \
            int u = tid + j*256; int row = u >> 2, kc = u & 3; \
            uint32_t sw = tunit(row, kc); \
            long ao = (long)(by*128 + row)*K + kof + kc*8; \
            long bo = (long)(bx*128 + row)*K + kof + kc*8; \
            CP16(st + sw,          A  + ao); \
            CP16(st + 8192 + sw,   Bh + bo); \
            CP16(st + 16384 + sw,  Bl + bo); \
        } \
        CP_COMMIT(); \
    } while (0)

    LOAD_W2(0, 0);
    LOAD_W2(1, 1);

    int lr = lane & 15, lk = lane >> 4;
    for (int ic = 0; ic < NC; ic++) {
        int s = ic - (ic/3)*3;
        if (ic + 1 < NC) CP_WAIT1(); else CP_WAIT0();
        __syncthreads();
        if (ic + 2 < NC) { int s2 = (ic+2) - ((ic+2)/3)*3; LOAD_W2(ic + 2, s2); }

        uint32_t pA = sb + s*STG2, pBh = pA + 8192, pBl = pA + 16384;
        #pragma unroll
        for (int ks = 0; ks < 2; ks++) {
            uint32_t a[2][4], bh[8][2], bl[8][2];
            #pragma unroll
            for (int mt = 0; mt < 2; mt++)
                ldsm_x4(a[mt], pA + tunit(wm*32 + mt*16 + lr, ks*2 + lk));
            #pragma unroll
            for (int bp = 0; bp < 4; bp++) {
                uint32_t off = tunit(wn*64 + bp*16 + lr, ks*2 + lk);
                uint32_t t[4];
                ldsm_x4(t, pBh + off);
                bh[bp*2][0]=t[0]; bh[bp*2][1]=t[2]; bh[bp*2+1][0]=t[1]; bh[bp*2+1][1]=t[3];
                ldsm_x4(t, pBl + off);
                bl[bp*2][0]=t[0]; bl[bp*2][1]=t[2]; bl[bp*2+1][0]=t[1]; bl[bp*2+1][1]=t[3];
            }
            #pragma unroll
            for (int mt = 0; mt < 2; mt++)
                #pragma unroll
                for (int nt = 0; nt < 8; nt++) {
                    mma16816f(acc[mt][nt], a[mt], bh[nt]);
                    mma16816f(acc[mt][nt], a[mt], bl[nt]);
                }
        }
    }

    #pragma unroll
    for (int mt = 0; mt < 2; mt++)
        #pragma unroll
        for (int nt = 0; nt < 8; nt++) {
            long r = by*128 + wm*32 + mt*16 + (lane >> 2);
            long c = bx*128 + wn*64 + nt*8 + (lane & 3)*2;
            *(float2*)&C[r*N + c]     = make_float2(acc[mt][nt][0], acc[mt][nt][1]);
            *(float2*)&C[(r+8)*N + c] = make_float2(acc[mt][nt][2], acc[mt][nt][3]);
        }
}

// ====== GEMM variant 2: A split + W split (3 MMA, ~fp32 accurate) =========
#define STG3 32768   // Ah 8K | Al 8K | Bh 8K | Bl 8K
__global__ __launch_bounds__(256) void gemm_f3(
    const __half* __restrict__ Ah, const __half* __restrict__ Al,
    const __half* __restrict__ Bh, const __half* __restrict__ Bl,
    float* __restrict__ C, int M, int N, int K)
{
    extern __shared__ __align__(128) char smem[];
    uint32_t sb = smem_to_u32(smem);
    int tid = threadIdx.x, lane = tid & 31, wid = tid >> 5;
    int wm = wid & 3, wn = wid >> 2;
    int bx = blockIdx.x, by = blockIdx.y;
    const int NC = K >> 5;

    float acc[2][8][4];
    #pragma unroll
    for (int i = 0; i < 2; i++)
        #pragma unroll
        for (int j = 0; j < 8; j++)
            #pragma unroll
            for (int q = 0; q < 4; q++) acc[i][j][q] = 0.f;

    #define LOAD_F3(ic, s) do { \
        long kof = (long)(ic) * 32; \
        uint32_t st = sb + (s)*STG3; \
        _Pragma("unroll") \
        for (int j = 0; j < 2; j++) { \
            int u = tid + j*256; int row = u >> 2, kc = u & 3; \
            uint32_t sw = tunit(row, kc); \
            long ao = (long)(by*128 + row)*K + kof + kc*8; \
            long bo = (long)(bx*128 + row)*K + kof + kc*8; \
            CP16(st + sw,          Ah + ao); \
            CP16(st + 8192 + sw,   Al + ao); \
            CP16(st + 16384 + sw,  Bh + bo); \
            CP16(st + 24576 + sw,  Bl + bo); \
        } \
        CP_COMMIT(); \
    } while (0)

    LOAD_F3(0, 0);
    LOAD_F3(1, 1);

    int lr = lane & 15, lk = lane >> 4;
    for (int ic = 0; ic < NC; ic++) {
        int s = ic - (ic/3)*3;
        if (ic + 1 < NC) CP_WAIT1(); else CP_WAIT0();
        __syncthreads();
        if (ic + 2 < NC) { int s2 = (ic+2) - ((ic+2)/3)*3; LOAD_F3(ic + 2, s2); }

        uint32_t pAh = sb + s*STG3, pAl = pAh + 8192;
        uint32_t pBh = pAh + 16384, pBl = pAh + 24576;
        #pragma unroll
        for (int ks = 0; ks < 2; ks++) {
            uint32_t ah[2][4], al[2][4], bh[8][2], bl[8][2];
            #pragma unroll
            for (int mt = 0; mt < 2; mt++) {
                uint32_t off = tunit(wm*32 + mt*16 + lr, ks*2 + lk);
                ldsm_x4(ah[mt], pAh + off);
                ldsm_x4(al[mt], pAl + off);
            }
            #pragma unroll
            for (int bp = 0; bp < 4; bp++) {
                uint32_t off = tunit(wn*64 + bp*16 + lr, ks*2 + lk);
                uint32_t t[4];
                ldsm_x4(t, pBh + off);
                bh[bp*2][0]=t[0]; bh[bp*2][1]=t[2]; bh[bp*2+1][0]=t[1]; bh[bp*2+1][1]=t[3];
                ldsm_x4(t, pBl + off);
                bl[bp*2][0]=t[0]; bl[bp*2][1]=t[2]; bl[bp*2+1][0]=t[1]; bl[bp*2+1][1]=t[3];
            }
            #pragma unroll
            for (int mt = 0; mt < 2; mt++)
                #pragma unroll
                for (int nt = 0; nt < 8; nt++) {
                    mma16816f(acc[mt][nt], ah[mt], bh[nt]);
                    mma16816f(acc[mt][nt], ah[mt], bl[nt]);
                    mma16816f(acc[mt][nt], al[mt], bh[nt]);
                }
        }
    }

    #pragma unroll
    for (int mt = 0; mt < 2; mt++)
        #pragma unroll
        for (int nt = 0; nt < 8; nt++) {
            long r = by*128 + wm*32 + mt*16 + (lane >> 2);
            long c = bx*128 + wn*64 + nt*8 + (lane & 3)*2;
            *(float2*)&C[r*N + c]     = make_float2(acc[mt][nt][0], acc[mt][nt][1]);
            *(float2*)&C[(r+8)*N + c] = make_float2(acc[mt][nt][2], acc[mt][nt][3]);
        }
}

// ======================= beta / g projections =============================
__global__ __launch_bounds__(256) void betag_kernel(
    const float* __restrict__ hid, const float* __restrict__ Wb,
    const float* __restrict__ Wa, const float* __restrict__ dtb,
    const float* __restrict__ Alog)
{
    int row = blockIdx.x;
    int tid = threadIdx.x;
    __shared__ float sh[D_];
    __shared__ float red[256];
    *(float4*)&sh[tid*4] = *(const float4*)(hid + (long)row*D_ + tid*4);
    __syncthreads();
    int c  = tid & 31, sg = tid >> 5;
    const float* W = (c < 16) ? Wb : Wa;
    int cc = c & 15, k0 = sg * 128;
    float acc = 0.f;
    #pragma unroll 8
    for (int k = 0; k < 128; k++)
        acc = fmaf(sh[k0 + k], W[(k0 + k)*HV_ + cc], acc);
    red[tid] = acc;
    __syncthreads();
    if (tid < 32) {
        float s = 0.f;
        #pragma unroll
        for (int si = 0; si < 8; si++) s += red[si*32 + c];
        if (c < 16) g_beta[(long)row*HV_ + cc] = 1.f / (1.f + expf(-s));
        else {
            float x  = s + dtb[cc];
            float sp = (x > 20.f) ? x : log1pf(expf(x));
            g_gg[(long)row*HV_ + cc] = -expf(Alog[cc]) * sp;
        }
    }
}

// ============== causal conv + SiLU + split + l2norm =======================
__global__ __launch_bounds__(256) void conv_kernel(const float* __restrict__ convw)
{
    int t = blockIdx.x, b = blockIdx.y;
    int tid = threadIdx.x;
    long row = (long)(b*T_ + t);
    __shared__ float sy[CONVD];
    #pragma unroll
    for (int j = 0; j < 8; j++) {
        int c = tid + j*256;
        float4 w = *(const float4*)(convw + c*4);
        float acc = g_mixed[row*MIXW + c] * w.w;
        if (t >= 1) acc = fmaf(g_mixed[(row-1)*MIXW + c], w.z, acc);
        if (t >= 2) acc = fmaf(g_mixed[(row-2)*MIXW + c], w.y, acc);
        if (t >= 3) acc = fmaf(g_mixed[(row-3)*MIXW + c], w.x, acc);
        sy[c] = acc / (1.f + __expf(-acc));
    }
    __syncthreads();
    int wrp = tid >> 5, lane = tid & 31;
    {
        float y0 = sy[wrp*64 + lane], y1 = sy[wrp*64 + 32 + lane];
        float ss = y0*y0 + y1*y1;
        #pragma unroll
        for (int off = 16; off; off >>= 1) ss += __shfl_xor_sync(0xffffffffu, ss, off);
        float rs = rsqrtf(ss + EPS_) * 0.125f;
        g_qn[(row*HK_ + wrp)*64 + lane]      = y0 * rs;
        g_qn[(row*HK_ + wrp)*64 + 32 + lane] = y1 * rs;
    }
    {
        float y0 = sy[KDIM_ + wrp*64 + lane], y1 = sy[KDIM_ + wrp*64 + 32 + lane];
        float ss = y0*y0 + y1*y1;
        #pragma unroll
        for (int off = 16; off; off >>= 1) ss += __shfl_xor_sync(0xffffffffu, ss, off);
        float rs = rsqrtf(ss + EPS_);
        g_kn[(row*HK_ + wrp)*64 + lane]      = y0 * rs;
        g_kn[(row*HK_ + wrp)*64 + 32 + lane] = y1 * rs;
    }
    #pragma unroll
    for (int j = 0; j < 4; j++) {
        int c = tid + j*256;
        g_v[row*VDIM_ + c] = sy[1024 + c];
    }
}

// ======= gated delta recurrence: R7 structure, depth-8 prefetch ===========
#define PF 8
__global__ __launch_bounds__(128) void recurrence_kernel()
{
    int w = blockIdx.x*4 + (threadIdx.x >> 5);    // 0..511
    int lane = threadIdx.x & 31;
    int bh = w >> 4, cg = w & 15;
    int b = bh >> 4, h = bh & 15, kh = h >> 1;
    int colIdx = lane >> 3, rseg = lane & 7;
    int col = cg*4 + colIdx;

    const float* kb = g_kn   + ((long)(b*T_)*HK_ + kh)*64 + rseg*8;
    const float* qb = g_qn   + ((long)(b*T_)*HK_ + kh)*64 + rseg*8;
    const float* vb = g_v    + ((long)(b*T_)*HV_ + h)*64 + col;
    const float* gb = g_gg   + (long)(b*T_)*HV_ + h;
    const float* bb = g_beta + (long)(b*T_)*HV_ + h;
    float*       ob = g_o    + ((long)(b*T_)*HV_ + h)*64 + col;
    const long qs = (long)HK_*64, vs = (long)HV_*64, gs = HV_;

    float S[8], kprev[8], dprev = 0.f;
    #pragma unroll
    for (int i = 0; i < 8; i++) { S[i] = 0.f; kprev[i] = 0.f; }

    float4 pk0[PF], pk1[PF], pq0[PF], pq1[PF];
    float  pv[PF], pg[PF], pb[PF];
    #pragma unroll
    for (int j = 0; j < PF; j++) {
        long o = j;
        pk0[j] = *(const float4*)(kb + o*qs);  pk1[j] = *(const float4*)(kb + o*qs + 4);
        pq0[j] = *(const float4*)(qb + o*qs);  pq1[j] = *(const float4*)(qb + o*qs + 4);
        pv[j] = vb[o*vs];  pg[j] = gb[o*gs];  pb[j] = bb[o*gs];
    }

    for (int t0 = 0; t0 < T_; t0 += PF) {
        #pragma unroll
        for (int j = 0; j < PF; j++) {
            int t = t0 + j;
            float4 k0 = pk0[j], k1 = pk1[j], q0 = pq0[j], q1 = pq1[j];
            float vv = pv[j], gv = pg[j], bv = pb[j];
            if (t + PF < T_) {
                long o = (long)(t + PF);
                pk0[j] = *(const float4*)(kb + o*qs);  pk1[j] = *(const float4*)(kb + o*qs + 4);
                pq0[j] = *(const float4*)(qb + o*qs);  pq1[j] = *(const float4*)(qb + o*qs + 4);
                pv[j] = vb[o*vs];  pg[j] = gb[o*gs];  pb[j] = bb[o*gs];
            }

            float eg = __expf(gv);
            float kc[8] = {k0.x,k0.y,k0.z,k0.w,k1.x,k1.y,k1.z,k1.w};
            float qc[8] = {q0.x,q0.y,q0.z,q0.w,q1.x,q1.y,q1.z,q1.w};
            float kva = 0.f, kvb2 = 0.f, oa = 0.f, ob2 = 0.f, qa = 0.f, qb2 = 0.f;
            #pragma unroll
            for (int i = 0; i < 4; i++) {
                S[i] = fmaf(kprev[i], dprev, S[i]) * eg;
                kva = fmaf(kc[i], S[i], kva);
                oa  = fmaf(qc[i], S[i], oa);
                qa  = fmaf(qc[i], kc[i], qa);
                kprev[i] = kc[i];
            }
            #pragma unroll
            for (int i = 4; i < 8; i++) {
                S[i] = fmaf(kprev[i], dprev, S[i]) * eg;
                kvb2 = fmaf(kc[i], S[i], kvb2);
                ob2  = fmaf(qc[i], S[i], ob2);
                qb2  = fmaf(qc[i], kc[i], qb2);
                kprev[i] = kc[i];
            }
            float kvp = kva + kvb2, op = oa + ob2, qkp = qa + qb2;
            #pragma unroll
            for (int off = 1; off < 8; off <<= 1) {
                kvp += __shfl_xor_sync(0xffffffffu, kvp, off);
                op  += __shfl_xor_sync(0xffffffffu, op,  off);
                qkp += __shfl_xor_sync(0xffffffffu, qkp, off);
            }
            float delta = (vv - kvp) * bv;
            if (rseg == 0) ob[(long)t*vs] = fmaf(qkp, delta, op);
            dprev = delta;
        }
    }
}

// ========== gated RMSNorm * silu(z), emits fp16 hi/lo for GEMM3 ===========
__global__ __launch_bounds__(256) void gnorm_kernel(const float* __restrict__ nw)
{
    int t = blockIdx.x, b = blockIdx.y;
    long row = (long)(b*T_ + t);
    int wrp = threadIdx.x >> 5, lane = threadIdx.x & 31;
    #pragma unroll
    for (int hh = wrp; hh < HV_; hh += 8) {
        float o0 = g_o[(row*HV_ + hh)*64 + lane];
        float o1 = g_o[(row*HV_ + hh)*64 + 32 + lane];
        float ss = o0*o0 + o1*o1;
        #pragma unroll
        for (int off = 16; off; off >>= 1) ss += __shfl_xor_sync(0xffffffffu, ss, off);
        float rs = rsqrtf(ss * (1.f/64.f) + EPS_);
        float z0 = g_mixed[row*MIXW + CONVD + hh*64 + lane];
        float z1 = g_mixed[row*MIXW + CONVD + hh*64 + 32 + lane];
        float v0 = o0 * rs * nw[lane]      * (z0 / (1.f + __expf(-z0)));
        float v1 = o1 * rs * nw[lane + 32] * (z1 / (1.f + __expf(-z1)));
        long i0 = row*VDIM_ + hh*64 + lane;
        __half h0 = __float2half(v0), h1 = __float2half(v1);
        g_onh[i0]      = h0;
        g_onh[i0 + 32] = h1;
        g_onl[i0]      = __float2half(v0 - __half2float(h0));
        g_onl[i0 + 32] = __float2half(v1 - __half2float(h1));
    }
}

// ==========================================================================
extern "C" void kernel_launch(void* const* d_in, const int* in_sizes, int n_in,
                              void* d_out, int out_size)
{
    (void)in_sizes; (void)n_in; (void)out_size;
    const float* hid   = (const float*)d_in[0];
    const float* Wqkv  = (const float*)d_in[1];
    const float* Wz    = (const float*)d_in[2];
    const float* Wb    = (const float*)d_in[3];
    const float* Wa    = (const float*)d_in[4];
    const float* dtb   = (const float*)d_in[5];
    const float* Alog  = (const float*)d_in[6];
    const float* convw = (const float*)d_in[7];
    const float* nw    = (const float*)d_in[8];
    const float* Wout  = (const float*)d_in[9];
    float* out = (float*)d_out;

    float *mixed;
    __half *hh, *w1h, *w1l, *woh, *wol, *onh, *onl;
    cudaGetSymbolAddress((void**)&mixed, g_mixed);
    cudaGetSymbolAddress((void**)&hh,  g_hid);
    cudaGetSymbolAddress((void**)&w1h, g_w1h);  cudaGetSymbolAddress((void**)&w1l, g_w1l);
    cudaGetSymbolAddress((void**)&woh, g_woh);  cudaGetSymbolAddress((void**)&wol, g_wol);
    cudaGetSymbolAddress((void**)&onh, g_onh);  cudaGetSymbolAddress((void**)&onl, g_onl);

    static int smem_set = 0;
    if (!smem_set) {
        cudaFuncSetAttribute(gemm_w2, cudaFuncAttributeMaxDynamicSharedMemorySize, 3*STG2);
        cudaFuncSetAttribute(gemm_f3, cudaFuncAttributeMaxDynamicSharedMemorySize, 3*STG3);
        smem_set = 1;
    }

    // conversions
    cvt_f2h<<<(NTOK*D_/4 + 255)/256, 256>>>(hid, hh, NTOK*D_/4);
    tconv_f2h2<<<dim3(CONVD/32, D_/32), dim3(32,8)>>>(Wqkv, w1h, w1l, D_, CONVD);
    tconv_f2h2<<<dim3(VDIM_/32, D_/32), dim3(32,8)>>>(Wz, w1h + (long)CONVD*D_, w1l + (long)CONVD*D_, D_, VDIM_);
    tconv_f2h2<<<dim3(D_/32, VDIM_/32), dim3(32,8)>>>(Wout, woh, wol, VDIM_, D_);

    // fused GEMM: [mixed | z] = hid @ [Wqkv | Wz]   (W compensated, 2 MMA)
    gemm_w2<<<dim3(MIXW/128, NTOK/128), 256, 3*STG2>>>(hh, w1h, w1l, mixed, NTOK, MIXW, D_);
    // beta / g
    betag_kernel<<<NTOK, 256>>>(hid, Wb, Wa, dtb, Alog);
    // conv + silu + split + l2norm
    conv_kernel<<<dim3(T_, B_), 256>>>(convw);
    // recurrence (depth-8 prefetch, 128 blocks x 4 warps)
    recurrence_kernel<<<128, 128>>>();
    // gated RMSNorm -> fp16 hi/lo
    gnorm_kernel<<<dim3(T_, B_), 256>>>(nw);
    // GEMM3: out = on @ Wout  (fully compensated, 3 MMA)
    gemm_f3<<<dim3(D_/128, NTOK/128), 256, 3*STG3>>>(onh, onl, woh, wol, out, NTOK, D_, VDIM_);
}

// round 14
// speedup vs baseline: 1.2663x; 1.1322x over previous
#include <cuda_runtime.h>
#include <cuda_fp16.h>
#include <math.h>
#include <stdint.h>

#define B_    2
#define T_    2048
#define D_    1024
#define HV_   16
#define HK_   8
#define KDIM_ 512
#define VDIM_ 1024
#define CONVD 2048
#define MIXW  3072          // fused GEMM width: [qkv 2048 | z 1024]
#define EPS_  1e-6f
#define NTOK  (B_*T_)       // 4096

// ======================= PTX helpers ======================================
__device__ __forceinline__ uint32_t smem_to_u32(const void* p) {
    uint32_t a;
    asm("{ .reg .u64 t; cvta.to.shared.u64 t, %1; cvt.u32.u64 %0, t; }" : "=r"(a) : "l"(p));
    return a;
}
__device__ __forceinline__ void ldsm_x4(uint32_t* r, uint32_t addr) {
    asm volatile("ldmatrix.sync.aligned.m8n8.x4.shared.b16 {%0,%1,%2,%3}, [%4];"
        : "=r"(r[0]), "=r"(r[1]), "=r"(r[2]), "=r"(r[3]) : "r"(addr));
}
__device__ __forceinline__ void mma16816f(float* c, const uint32_t* a, const uint32_t* b) {
    asm volatile("mma.sync.aligned.m16n8k16.row.col.f32.f16.f16.f32 "
        "{%0,%1,%2,%3}, {%4,%5,%6,%7}, {%8,%9}, {%0,%1,%2,%3};"
        : "+f"(c[0]), "+f"(c[1]), "+f"(c[2]), "+f"(c[3])
        : "r"(a[0]), "r"(a[1]), "r"(a[2]), "r"(a[3]), "r"(b[0]), "r"(b[1]));
}
#define CP16(sm, gp) asm volatile("cp.async.cg.shared.global [%0], [%1], 16;" :: "r"(sm), "l"(gp))
#define CP_COMMIT()  asm volatile("cp.async.commit_group;" ::: "memory")
#define CP_WAIT1()   asm volatile("cp.async.wait_group 1;" ::: "memory")
#define CP_WAIT0()   asm volatile("cp.async.wait_group 0;" ::: "memory")

// byte offset of (row, kc) 16B-unit in a [128 x 32fp16] tile, xor-swizzled
__device__ __forceinline__ uint32_t tunit(int row, int kc) {
    return (uint32_t)((row*4 + (kc ^ ((row >> 1) & 3))) * 16);
}

// ======================= static scratch ===================================
__device__ float g_mixed[NTOK*MIXW];        // [qkv | z]
__device__ float g_beta[NTOK*HV_];
__device__ float g_gg[NTOK*HV_];
__device__ float g_qn[NTOK*HK_*64];
__device__ float g_kn[NTOK*HK_*64];
__device__ float g_v[NTOK*VDIM_];
__device__ float g_o[NTOK*VDIM_];
__device__ __half g_hid[NTOK*D_];
__device__ __half g_w1[MIXW*D_];                      // [N=3072,K] fp16 single
__device__ __half g_woh[D_*VDIM_], g_wol[D_*VDIM_];   // [N=1024,K] hi/lo
__device__ __half g_onh[NTOK*VDIM_], g_onl[NTOK*VDIM_];

// ======================= fp32 -> fp16 (elementwise) =======================
__global__ __launch_bounds__(256) void cvt_f2h(const float* __restrict__ src,
        __half* __restrict__ dst, int n4)
{
    int i = blockIdx.x*256 + threadIdx.x;
    if (i >= n4) return;
    float4 x = ((const float4*)src)[i];
    ((__half2*)dst)[2*i]   = __floats2half2_rn(x.x, x.y);
    ((__half2*)dst)[2*i+1] = __floats2half2_rn(x.z, x.w);
}

// ===== transpose + convert: W[K,N] fp32 -> Wt[N,K] fp16 (single) ==========
__global__ __launch_bounds__(256) void tconv_f2h(const float* __restrict__ W,
        __half* __restrict__ Wt, int K, int N)
{
    __shared__ float tile[32][33];
    int n0 = blockIdx.x*32, k0 = blockIdx.y*32;
    int tx = threadIdx.x, ty = threadIdx.y;   // 32 x 8
    #pragma unroll
    for (int j = 0; j < 32; j += 8)
        tile[ty+j][tx] = W[(long)(k0+ty+j)*N + n0 + tx];
    __syncthreads();
    #pragma unroll
    for (int j = 0; j < 32; j += 8)
        Wt[(long)(n0+ty+j)*K + k0 + tx] = __float2half(tile[tx][ty+j]);
}

// ===== transpose + convert: W[K,N] fp32 -> Wt[N,K] fp16 hi/lo =============
__global__ __launch_bounds__(256) void tconv_f2h2(const float* __restrict__ W,
        __half* __restrict__ Wh, __half* __restrict__ Wl, int K, int N)
{
    __shared__ float tile[32][33];
    int n0 = blockIdx.x*32, k0 = blockIdx.y*32;
    int tx = threadIdx.x, ty = threadIdx.y;   // 32 x 8
    #pragma unroll
    for (int j = 0; j < 32; j += 8)
        tile[ty+j][tx] = W[(long)(k0+ty+j)*N + n0 + tx];
    __syncthreads();
    #pragma unroll
    for (int j = 0; j < 32; j += 8) {
        float x = tile[tx][ty+j];
        __half h = __float2half(x);
        long o = (long)(n0+ty+j)*K + k0 + tx;
        Wh[o] = h;
        Wl[o] = __float2half(x - __half2float(h));
    }
}

// =============== GEMM variant 0: single fp16 MMA (R5-proven) ==============
#define STG1 16384   // A 8K | B 8K
__global__ __launch_bounds__(256) void gemm_h1(
    const __half* __restrict__ A, const __half* __restrict__ Bm,
    float* __restrict__ C, int M, int N, int K)
{
    extern __shared__ __align__(128) char smem[];
    uint32_t sb = smem_to_u32(smem);
    int tid = threadIdx.x, lane = tid & 31, wid = tid >> 5;
    int wm = wid & 3, wn = wid >> 2;        // 4 x 2 warp grid (32x64 per warp)
    int bx = blockIdx.x, by = blockIdx.y;
    const int NC = K >> 5;

    float acc[2][8][4];
    #pragma unroll
    for (int i = 0; i < 2; i++)
        #pragma unroll
        for (int j = 0; j < 8; j++)
            #pragma unroll
            for (int q = 0; q < 4; q++) acc[i][j][q] = 0.f;

    #define LOAD_H1(ic, s) do { \
        long kof = (long)(ic) * 32; \
        uint32_t st = sb + (s)*STG1; \
        _Pragma("unroll") \
        for (int j = 0; j < 2; j++) { \
            int u = tid + j*256; \
            int row = u >> 2, kc = u & 3; \
            CP16(st + tunit(row, kc), A + (long)(by*128 + row)*K + kof + kc*8); \
        } \
        _Pragma("unroll") \
        for (int j = 0; j < 2; j++) { \
            int u = tid + j*256; \
            int row = u >> 2, kc = u & 3; \
            CP16(st + 8192 + tunit(row, kc), Bm + (long)(bx*128 + row)*K + kof + kc*8); \
        } \
        CP_COMMIT(); \
    } while (0)

    LOAD_H1(0, 0);
    LOAD_H1(1, 1);

    int lr = lane & 15, lk = lane >> 4;
    for (int ic = 0; ic < NC; ic++) {
        int s = ic - (ic/3)*3;
        if (ic + 1 < NC) CP_WAIT1(); else CP_WAIT0();
        __syncthreads();
        if (ic + 2 < NC) { int s2 = (ic+2) - ((ic+2)/3)*3; LOAD_H1(ic + 2, s2); }

        uint32_t pA = sb + s*STG1, pB = pA + 8192;
        #pragma unroll
        for (int ks = 0; ks < 2; ks++) {
            uint32_t a[2][4], b[8][2];
            #pragma unroll
            for (int mt = 0; mt < 2; mt++)
                ldsm_x4(a[mt], pA + tunit(wm*32 + mt*16 + lr, ks*2 + lk));
            #pragma unroll
            for (int bp = 0; bp < 4; bp++) {
                uint32_t t[4];
                ldsm_x4(t, pB + tunit(wn*64 + bp*16 + lr, ks*2 + lk));
                b[bp*2][0]=t[0]; b[bp*2][1]=t[2]; b[bp*2+1][0]=t[1]; b[bp*2+1][1]=t[3];
            }
            #pragma unroll
            for (int mt = 0; mt < 2; mt++)
                #pragma unroll
                for (int nt = 0; nt < 8; nt++)
                    mma16816f(acc[mt][nt], a[mt], b[nt]);
        }
    }

    #pragma unroll
    for (int mt = 0; mt < 2; mt++)
        #pragma unroll
        for (int nt = 0; nt < 8; nt++) {
            long r = by*128 + wm*32 + mt*16 + (lane >> 2);
            long c = bx*128 + wn*64 + nt*8 + (lane & 3)*2;
            *(float2*)&C[r*N + c]     = make_float2(acc[mt][nt][0], acc[mt][nt][1]);
            *(float2*)&C[(r+8)*N + c] = make_float2(acc[mt][nt][2], acc[mt][nt][3]);
        }
}

// ====== GEMM variant 2: A split + W split (3 MMA, ~fp32 accurate) =========
#define STG3 32768   // Ah 8K | Al 8K | Bh 8K | Bl 8K
__global__ __launch_bounds__(256) void gemm_f3(
    const __half* __restrict__ Ah, const __half* __restrict__ Al,
    const __half* __restrict__ Bh, const __half* __restrict__ Bl,
    float* __restrict__ C, int M, int N, int K)
{
    extern __shared__ __align__(128) char smem[];
    uint32_t sb = smem_to_u32(smem);
    int tid = threadIdx.x, lane = tid & 31, wid = tid >> 5;
    int wm = wid & 3, wn = wid >> 2;
    int bx = blockIdx.x, by = blockIdx.y;
    const int NC = K >> 5;

    float acc[2][8][4];
    #pragma unroll
    for (int i = 0; i < 2; i++)
        #pragma unroll
        for (int j = 0; j < 8; j++)
            #pragma unroll
            for (int q = 0; q < 4; q++) acc[i][j][q] = 0.f;

    #define LOAD_F3(ic, s) do { \
        long kof = (long)(ic) * 32; \
        uint32_t st = sb + (s)*STG3; \
        _Pragma("unroll") \
        for (int j = 0; j < 2; j++) { \
            int u = tid + j*256; int row = u >> 2, kc = u & 3; \
            uint32_t sw = tunit(row, kc); \
            long ao = (long)(by*128 + row)*K + kof + kc*8; \
            long bo = (long)(bx*128 + row)*K + kof + kc*8; \
            CP16(st + sw,          Ah + ao); \
            CP16(st + 8192 + sw,   Al + ao); \
            CP16(st + 16384 + sw,  Bh + bo); \
            CP16(st + 24576 + sw,  Bl + bo); \
        } \
        CP_COMMIT(); \
    } while (0)

    LOAD_F3(0, 0);
    LOAD_F3(1, 1);

    int lr = lane & 15, lk = lane >> 4;
    for (int ic = 0; ic < NC; ic++) {
        int s = ic - (ic/3)*3;
        if (ic + 1 < NC) CP_WAIT1(); else CP_WAIT0();
        __syncthreads();
        if (ic + 2 < NC) { int s2 = (ic+2) - ((ic+2)/3)*3; LOAD_F3(ic + 2, s2); }

        uint32_t pAh = sb + s*STG3, pAl = pAh + 8192;
        uint32_t pBh = pAh + 16384, pBl = pAh + 24576;
        #pragma unroll
        for (int ks = 0; ks < 2; ks++) {
            uint32_t ah[2][4], al[2][4], bh[8][2], bl[8][2];
            #pragma unroll
            for (int mt = 0; mt < 2; mt++) {
                uint32_t off = tunit(wm*32 + mt*16 + lr, ks*2 + lk);
                ldsm_x4(ah[mt], pAh + off);
                ldsm_x4(al[mt], pAl + off);
            }
            #pragma unroll
            for (int bp = 0; bp < 4; bp++) {
                uint32_t off = tunit(wn*64 + bp*16 + lr, ks*2 + lk);
                uint32_t t[4];
                ldsm_x4(t, pBh + off);
                bh[bp*2][0]=t[0]; bh[bp*2][1]=t[2]; bh[bp*2+1][0]=t[1]; bh[bp*2+1][1]=t[3];
                ldsm_x4(t, pBl + off);
                bl[bp*2][0]=t[0]; bl[bp*2][1]=t[2]; bl[bp*2+1][0]=t[1]; bl[bp*2+1][1]=t[3];
            }
            #pragma unroll
            for (int mt = 0; mt < 2; mt++)
                #pragma unroll
                for (int nt = 0; nt < 8; nt++) {
                    mma16816f(acc[mt][nt], ah[mt], bh[nt]);
                    mma16816f(acc[mt][nt], ah[mt], bl[nt]);
                    mma16816f(acc[mt][nt], al[mt], bh[nt]);
                }
        }
    }

    #pragma unroll
    for (int mt = 0; mt < 2; mt++)
        #pragma unroll
        for (int nt = 0; nt < 8; nt++) {
            long r = by*128 + wm*32 + mt*16 + (lane >> 2);
            long c = bx*128 + wn*64 + nt*8 + (lane & 3)*2;
            *(float2*)&C[r*N + c]     = make_float2(acc[mt][nt][0], acc[mt][nt][1]);
            *(float2*)&C[(r+8)*N + c] = make_float2(acc[mt][nt][2], acc[mt][nt][3]);
        }
}

// ======================= beta / g projections =============================
__global__ __launch_bounds__(256) void betag_kernel(
    const float* __restrict__ hid, const float* __restrict__ Wb,
    const float* __restrict__ Wa, const float* __restrict__ dtb,
    const float* __restrict__ Alog)
{
    int row = blockIdx.x;
    int tid = threadIdx.x;
    __shared__ float sh[D_];
    __shared__ float red[256];
    *(float4*)&sh[tid*4] = *(const float4*)(hid + (long)row*D_ + tid*4);
    __syncthreads();
    int c  = tid & 31, sg = tid >> 5;
    const float* W = (c < 16) ? Wb : Wa;
    int cc = c & 15, k0 = sg * 128;
    float acc = 0.f;
    #pragma unroll 8
    for (int k = 0; k < 128; k++)
        acc = fmaf(sh[k0 + k], W[(k0 + k)*HV_ + cc], acc);
    red[tid] = acc;
    __syncthreads();
    if (tid < 32) {
        float s = 0.f;
        #pragma unroll
        for (int si = 0; si < 8; si++) s += red[si*32 + c];
        if (c < 16) g_beta[(long)row*HV_ + cc] = 1.f / (1.f + expf(-s));
        else {
            float x  = s + dtb[cc];
            float sp = (x > 20.f) ? x : log1pf(expf(x));
            g_gg[(long)row*HV_ + cc] = -expf(Alog[cc]) * sp;
        }
    }
}

// ============== causal conv + SiLU + split + l2norm =======================
__global__ __launch_bounds__(256) void conv_kernel(const float* __restrict__ convw)
{
    int t = blockIdx.x, b = blockIdx.y;
    int tid = threadIdx.x;
    long row = (long)(b*T_ + t);
    __shared__ float sy[CONVD];
    #pragma unroll
    for (int j = 0; j < 8; j++) {
        int c = tid + j*256;
        float4 w = *(const float4*)(convw + c*4);
        float acc = g_mixed[row*MIXW + c] * w.w;
        if (t >= 1) acc = fmaf(g_mixed[(row-1)*MIXW + c], w.z, acc);
        if (t >= 2) acc = fmaf(g_mixed[(row-2)*MIXW + c], w.y, acc);
        if (t >= 3) acc = fmaf(g_mixed[(row-3)*MIXW + c], w.x, acc);
        sy[c] = acc / (1.f + __expf(-acc));
    }
    __syncthreads();
    int wrp = tid >> 5, lane = tid & 31;
    {
        float y0 = sy[wrp*64 + lane], y1 = sy[wrp*64 + 32 + lane];
        float ss = y0*y0 + y1*y1;
        #pragma unroll
        for (int off = 16; off; off >>= 1) ss += __shfl_xor_sync(0xffffffffu, ss, off);
        float rs = rsqrtf(ss + EPS_) * 0.125f;
        g_qn[(row*HK_ + wrp)*64 + lane]      = y0 * rs;
        g_qn[(row*HK_ + wrp)*64 + 32 + lane] = y1 * rs;
    }
    {
        float y0 = sy[KDIM_ + wrp*64 + lane], y1 = sy[KDIM_ + wrp*64 + 32 + lane];
        float ss = y0*y0 + y1*y1;
        #pragma unroll
        for (int off = 16; off; off >>= 1) ss += __shfl_xor_sync(0xffffffffu, ss, off);
        float rs = rsqrtf(ss + EPS_);
        g_kn[(row*HK_ + wrp)*64 + lane]      = y0 * rs;
        g_kn[(row*HK_ + wrp)*64 + 32 + lane] = y1 * rs;
    }
    #pragma unroll
    for (int j = 0; j < 4; j++) {
        int c = tid + j*256;
        g_v[row*VDIM_ + c] = sy[1024 + c];
    }
}

// ======= gated delta recurrence: depth-4 prefetch (R7 verbatim) ===========
#define PF 4
__global__ __launch_bounds__(128) void recurrence_kernel()
{
    int w = blockIdx.x*4 + (threadIdx.x >> 5);    // 0..511
    int lane = threadIdx.x & 31;
    int bh = w >> 4, cg = w & 15;
    int b = bh >> 4, h = bh & 15, kh = h >> 1;
    int colIdx = lane >> 3, rseg = lane & 7;
    int col = cg*4 + colIdx;

    const float* kb = g_kn   + ((long)(b*T_)*HK_ + kh)*64 + rseg*8;
    const float* qb = g_qn   + ((long)(b*T_)*HK_ + kh)*64 + rseg*8;
    const float* vb = g_v    + ((long)(b*T_)*HV_ + h)*64 + col;
    const float* gb = g_gg   + (long)(b*T_)*HV_ + h;
    const float* bb = g_beta + (long)(b*T_)*HV_ + h;
    float*       ob = g_o    + ((long)(b*T_)*HV_ + h)*64 + col;
    const long qs = (long)HK_*64, vs = (long)HV_*64, gs = HV_;

    float S[8], kprev[8], dprev = 0.f;
    #pragma unroll
    for (int i = 0; i < 8; i++) { S[i] = 0.f; kprev[i] = 0.f; }

    float4 pk0[PF], pk1[PF], pq0[PF], pq1[PF];
    float  pv[PF], pg[PF], pb[PF];
    #pragma unroll
    for (int j = 0; j < PF; j++) {
        long o = j;
        pk0[j] = *(const float4*)(kb + o*qs);  pk1[j] = *(const float4*)(kb + o*qs + 4);
        pq0[j] = *(const float4*)(qb + o*qs);  pq1[j] = *(const float4*)(qb + o*qs + 4);
        pv[j] = vb[o*vs];  pg[j] = gb[o*gs];  pb[j] = bb[o*gs];
    }

    for (int t0 = 0; t0 < T_; t0 += PF) {
        #pragma unroll
        for (int j = 0; j < PF; j++) {
            int t = t0 + j;
            float4 k0 = pk0[j], k1 = pk1[j], q0 = pq0[j], q1 = pq1[j];
            float vv = pv[j], gv = pg[j], bv = pb[j];
            if (t + PF < T_) {
                long o = (long)(t + PF);
                pk0[j] = *(const float4*)(kb + o*qs);  pk1[j] = *(const float4*)(kb + o*qs + 4);
                pq0[j] = *(const float4*)(qb + o*qs);  pq1[j] = *(const float4*)(qb + o*qs + 4);
                pv[j] = vb[o*vs];  pg[j] = gb[o*gs];  pb[j] = bb[o*gs];
            }

            float eg = __expf(gv);
            float kc[8] = {k0.x,k0.y,k0.z,k0.w,k1.x,k1.y,k1.z,k1.w};
            float qc[8] = {q0.x,q0.y,q0.z,q0.w,q1.x,q1.y,q1.z,q1.w};
            float kva = 0.f, kvb2 = 0.f, oa = 0.f, ob2 = 0.f, qa = 0.f, qb2 = 0.f;
            #pragma unroll
            for (int i = 0; i < 4; i++) {
                S[i] = fmaf(kprev[i], dprev, S[i]) * eg;
                kva = fmaf(kc[i], S[i], kva);
                oa  = fmaf(qc[i], S[i], oa);
                qa  = fmaf(qc[i], kc[i], qa);
                kprev[i] = kc[i];
            }
            #pragma unroll
            for (int i = 4; i < 8; i++) {
                S[i] = fmaf(kprev[i], dprev, S[i]) * eg;
                kvb2 = fmaf(kc[i], S[i], kvb2);
                ob2  = fmaf(qc[i], S[i], ob2);
                qb2  = fmaf(qc[i], kc[i], qb2);
                kprev[i] = kc[i];
            }
            float kvp = kva + kvb2, op = oa + ob2, qkp = qa + qb2;
            #pragma unroll
            for (int off = 1; off < 8; off <<= 1) {
                kvp += __shfl_xor_sync(0xffffffffu, kvp, off);
                op  += __shfl_xor_sync(0xffffffffu, op,  off);
                qkp += __shfl_xor_sync(0xffffffffu, qkp, off);
            }
            float delta = (vv - kvp) * bv;
            if (rseg == 0) ob[(long)t*vs] = fmaf(qkp, delta, op);
            dprev = delta;
        }
    }
}

// ========== gated RMSNorm * silu(z), emits fp16 hi/lo for GEMM3 ===========
__global__ __launch_bounds__(256) void gnorm_kernel(const float* __restrict__ nw)
{
    int t = blockIdx.x, b = blockIdx.y;
    long row = (long)(b*T_ + t);
    int wrp = threadIdx.x >> 5, lane = threadIdx.x & 31;
    #pragma unroll
    for (int hh = wrp; hh < HV_; hh += 8) {
        float o0 = g_o[(row*HV_ + hh)*64 + lane];
        float o1 = g_o[(row*HV_ + hh)*64 + 32 + lane];
        float ss = o0*o0 + o1*o1;
        #pragma unroll
        for (int off = 16; off; off >>= 1) ss += __shfl_xor_sync(0xffffffffu, ss, off);
        float rs = rsqrtf(ss * (1.f/64.f) + EPS_);
        float z0 = g_mixed[row*MIXW + CONVD + hh*64 + lane];
        float z1 = g_mixed[row*MIXW + CONVD + hh*64 + 32 + lane];
        float v0 = o0 * rs * nw[lane]      * (z0 / (1.f + __expf(-z0)));
        float v1 = o1 * rs * nw[lane + 32] * (z1 / (1.f + __expf(-z1)));
        long i0 = row*VDIM_ + hh*64 + lane;
        __half h0 = __float2half(v0), h1 = __float2half(v1);
        g_onh[i0]      = h0;
        g_onh[i0 + 32] = h1;
        g_onl[i0]      = __float2half(v0 - __half2float(h0));
        g_onl[i0 + 32] = __float2half(v1 - __half2float(h1));
    }
}

// ==========================================================================
extern "C" void kernel_launch(void* const* d_in, const int* in_sizes, int n_in,
                              void* d_out, int out_size)
{
    (void)in_sizes; (void)n_in; (void)out_size;
    const float* hid   = (const float*)d_in[0];
    const float* Wqkv  = (const float*)d_in[1];
    const float* Wz    = (const float*)d_in[2];
    const float* Wb    = (const float*)d_in[3];
    const float* Wa    = (const float*)d_in[4];
    const float* dtb   = (const float*)d_in[5];
    const float* Alog  = (const float*)d_in[6];
    const float* convw = (const float*)d_in[7];
    const float* nw    = (const float*)d_in[8];
    const float* Wout  = (const float*)d_in[9];
    float* out = (float*)d_out;

    float *mixed;
    __half *hh, *w1, *woh, *wol, *onh, *onl;
    cudaGetSymbolAddress((void**)&mixed, g_mixed);
    cudaGetSymbolAddress((void**)&hh,  g_hid);
    cudaGetSymbolAddress((void**)&w1,  g_w1);
    cudaGetSymbolAddress((void**)&woh, g_woh);  cudaGetSymbolAddress((void**)&wol, g_wol);
    cudaGetSymbolAddress((void**)&onh, g_onh);  cudaGetSymbolAddress((void**)&onl, g_onl);

    static int smem_set = 0;
    if (!smem_set) {
        cudaFuncSetAttribute(gemm_h1, cudaFuncAttributeMaxDynamicSharedMemorySize, 3*STG1);
        cudaFuncSetAttribute(gemm_f3, cudaFuncAttributeMaxDynamicSharedMemorySize, 3*STG3);
        smem_set = 1;
    }

    // conversions
    cvt_f2h<<<(NTOK*D_/4 + 255)/256, 256>>>(hid, hh, NTOK*D_/4);
    tconv_f2h<<<dim3(CONVD/32, D_/32), dim3(32,8)>>>(Wqkv, w1, D_, CONVD);
    tconv_f2h<<<dim3(VDIM_/32, D_/32), dim3(32,8)>>>(Wz, w1 + (long)CONVD*D_, D_, VDIM_);
    tconv_f2h2<<<dim3(D_/32, VDIM_/32), dim3(32,8)>>>(Wout, woh, wol, VDIM_, D_);

    // fused GEMM: [mixed | z] = hid @ [Wqkv | Wz]   (single fp16 MMA)
    gemm_h1<<<dim3(MIXW/128, NTOK/128), 256, 3*STG1>>>(hh, w1, mixed, NTOK, MIXW, D_);
    // beta / g
    betag_kernel<<<NTOK, 256>>>(hid, Wb, Wa, dtb, Alog);
    // conv + silu + split + l2norm
    conv_kernel<<<dim3(T_, B_), 256>>>(convw);
    // recurrence (depth-4 prefetch, 128 blocks x 4 warps — R7 verbatim)
    recurrence_kernel<<<128, 128>>>();
    // gated RMSNorm -> fp16 hi/lo
    gnorm_kernel<<<dim3(T_, B_), 256>>>(nw);
    // GEMM3: out = on @ Wout  (fully compensated, 3 MMA)
    gemm_f3<<<dim3(D_/128, NTOK/128), 256, 3*STG3>>>(onh, onl, woh, wol, out, NTOK, D_, VDIM_);
}

// round 15
// speedup vs baseline: 1.2881x; 1.0172x over previous
#include <cuda_runtime.h>
#include <cuda_fp16.h>
#include <math.h>
#include <stdint.h>

#define B_    2
#define T_    2048
#define D_    1024
#define HV_   16
#define HK_   8
#define KDIM_ 512
#define VDIM_ 1024
#define CONVD 2048
#define MIXW  3072          // fused GEMM width: [qkv 2048 | z 1024]
#define EPS_  1e-6f
#define NTOK  (B_*T_)       // 4096

// ======================= PTX helpers ======================================
__device__ __forceinline__ uint32_t smem_to_u32(const void* p) {
    uint32_t a;
    asm("{ .reg .u64 t; cvta.to.shared.u64 t, %1; cvt.u32.u64 %0, t; }" : "=r"(a) : "l"(p));
    return a;
}
__device__ __forceinline__ void ldsm_x4(uint32_t* r, uint32_t addr) {
    asm volatile("ldmatrix.sync.aligned.m8n8.x4.shared.b16 {%0,%1,%2,%3}, [%4];"
        : "=r"(r[0]), "=r"(r[1]), "=r"(r[2]), "=r"(r[3]) : "r"(addr));
}
__device__ __forceinline__ void mma16816f(float* c, const uint32_t* a, const uint32_t* b) {
    asm volatile("mma.sync.aligned.m16n8k16.row.col.f32.f16.f16.f32 "
        "{%0,%1,%2,%3}, {%4,%5,%6,%7}, {%8,%9}, {%0,%1,%2,%3};"
        : "+f"(c[0]), "+f"(c[1]), "+f"(c[2]), "+f"(c[3])
        : "r"(a[0]), "r"(a[1]), "r"(a[2]), "r"(a[3]), "r"(b[0]), "r"(b[1]));
}
#define CP16(sm, gp) asm volatile("cp.async.cg.shared.global [%0], [%1], 16;" :: "r"(sm), "l"(gp))
#define CP_COMMIT()  asm volatile("cp.async.commit_group;" ::: "memory")
#define CP_WAIT1()   asm volatile("cp.async.wait_group 1;" ::: "memory")
#define CP_WAIT0()   asm volatile("cp.async.wait_group 0;" ::: "memory")

// byte offset of (row, kc) 16B-unit in a [128 x 32fp16] tile, xor-swizzled
__device__ __forceinline__ uint32_t tunit(int row, int kc) {
    return (uint32_t)((row*4 + (kc ^ ((row >> 1) & 3))) * 16);
}

// ======================= static scratch ===================================
__device__ float g_mixed[NTOK*MIXW];        // [qkv | z]
__device__ float g_beta[NTOK*HV_];
__device__ float g_gg[NTOK*HV_];
__device__ float g_qn[NTOK*HK_*64];
__device__ float g_kn[NTOK*HK_*64];
__device__ float g_v[NTOK*VDIM_];
__device__ float g_o[NTOK*VDIM_];
__device__ __half g_hid[NTOK*D_];
__device__ __half g_w1[MIXW*D_];                      // [N=3072,K] fp16 single
__device__ __half g_woh[D_*VDIM_], g_wol[D_*VDIM_];   // [N=1024,K] hi/lo
__device__ __half g_on[NTOK*VDIM_];

// ======================= fp32 -> fp16 (elementwise) =======================
__global__ __launch_bounds__(256) void cvt_f2h(const float* __restrict__ src,
        __half* __restrict__ dst, int n4)
{
    int i = blockIdx.x*256 + threadIdx.x;
    if (i >= n4) return;
    float4 x = ((const float4*)src)[i];
    ((__half2*)dst)[2*i]   = __floats2half2_rn(x.x, x.y);
    ((__half2*)dst)[2*i+1] = __floats2half2_rn(x.z, x.w);
}

// ===== transpose + convert: W[K,N] fp32 -> Wt[N,K] fp16 (single) ==========
__global__ __launch_bounds__(256) void tconv_f2h(const float* __restrict__ W,
        __half* __restrict__ Wt, int K, int N)
{
    __shared__ float tile[32][33];
    int n0 = blockIdx.x*32, k0 = blockIdx.y*32;
    int tx = threadIdx.x, ty = threadIdx.y;   // 32 x 8
    #pragma unroll
    for (int j = 0; j < 32; j += 8)
        tile[ty+j][tx] = W[(long)(k0+ty+j)*N + n0 + tx];
    __syncthreads();
    #pragma unroll
    for (int j = 0; j < 32; j += 8)
        Wt[(long)(n0+ty+j)*K + k0 + tx] = __float2half(tile[tx][ty+j]);
}

// ===== transpose + convert: W[K,N] fp32 -> Wt[N,K] fp16 hi/lo =============
__global__ __launch_bounds__(256) void tconv_f2h2(const float* __restrict__ W,
        __half* __restrict__ Wh, __half* __restrict__ Wl, int K, int N)
{
    __shared__ float tile[32][33];
    int n0 = blockIdx.x*32, k0 = blockIdx.y*32;
    int tx = threadIdx.x, ty = threadIdx.y;   // 32 x 8
    #pragma unroll
    for (int j = 0; j < 32; j += 8)
        tile[ty+j][tx] = W[(long)(k0+ty+j)*N + n0 + tx];
    __syncthreads();
    #pragma unroll
    for (int j = 0; j < 32; j += 8) {
        float x = tile[tx][ty+j];
        __half h = __float2half(x);
        long o = (long)(n0+ty+j)*K + k0 + tx;
        Wh[o] = h;
        Wl[o] = __float2half(x - __half2float(h));
    }
}

// =============== GEMM variant 0: single fp16 MMA ==========================
#define STG1 16384   // A 8K | B 8K
__global__ __launch_bounds__(256) void gemm_h1(
    const __half* __restrict__ A, const __half* __restrict__ Bm,
    float* __restrict__ C, int M, int N, int K)
{
    extern __shared__ __align__(128) char smem[];
    uint32_t sb = smem_to_u32(smem);
    int tid = threadIdx.x, lane = tid & 31, wid = tid >> 5;
    int wm = wid & 3, wn = wid >> 2;        // 4 x 2 warp grid (32x64 per warp)
    int bx = blockIdx.x, by = blockIdx.y;
    const int NC = K >> 5;

    float acc[2][8][4];
    #pragma unroll
    for (int i = 0; i < 2; i++)
        #pragma unroll
        for (int j = 0; j < 8; j++)
            #pragma unroll
            for (int q = 0; q < 4; q++) acc[i][j][q] = 0.f;

    #define LOAD_H1(ic, s) do { \
        long kof = (long)(ic) * 32; \
        uint32_t st = sb + (s)*STG1; \
        _Pragma("unroll") \
        for (int j = 0; j < 2; j++) { \
            int u = tid + j*256; \
            int row = u >> 2, kc = u & 3; \
            CP16(st + tunit(row, kc), A + (long)(by*128 + row)*K + kof + kc*8); \
        } \
        _Pragma("unroll") \
        for (int j = 0; j < 2; j++) { \
            int u = tid + j*256; \
            int row = u >> 2, kc = u & 3; \
            CP16(st + 8192 + tunit(row, kc), Bm + (long)(bx*128 + row)*K + kof + kc*8); \
        } \
        CP_COMMIT(); \
    } while (0)

    LOAD_H1(0, 0);
    LOAD_H1(1, 1);

    int lr = lane & 15, lk = lane >> 4;
    for (int ic = 0; ic < NC; ic++) {
        int s = ic - (ic/3)*3;
        if (ic + 1 < NC) CP_WAIT1(); else CP_WAIT0();
        __syncthreads();
        if (ic + 2 < NC) { int s2 = (ic+2) - ((ic+2)/3)*3; LOAD_H1(ic + 2, s2); }

        uint32_t pA = sb + s*STG1, pB = pA + 8192;
        #pragma unroll
        for (int ks = 0; ks < 2; ks++) {
            uint32_t a[2][4], b[8][2];
            #pragma unroll
            for (int mt = 0; mt < 2; mt++)
                ldsm_x4(a[mt], pA + tunit(wm*32 + mt*16 + lr, ks*2 + lk));
            #pragma unroll
            for (int bp = 0; bp < 4; bp++) {
                uint32_t t[4];
                ldsm_x4(t, pB + tunit(wn*64 + bp*16 + lr, ks*2 + lk));
                b[bp*2][0]=t[0]; b[bp*2][1]=t[2]; b[bp*2+1][0]=t[1]; b[bp*2+1][1]=t[3];
            }
            #pragma unroll
            for (int mt = 0; mt < 2; mt++)
                #pragma unroll
                for (int nt = 0; nt < 8; nt++)
                    mma16816f(acc[mt][nt], a[mt], b[nt]);
        }
    }

    #pragma unroll
    for (int mt = 0; mt < 2; mt++)
        #pragma unroll
        for (int nt = 0; nt < 8; nt++) {
            long r = by*128 + wm*32 + mt*16 + (lane >> 2);
            long c = bx*128 + wn*64 + nt*8 + (lane & 3)*2;
            *(float2*)&C[r*N + c]     = make_float2(acc[mt][nt][0], acc[mt][nt][1]);
            *(float2*)&C[(r+8)*N + c] = make_float2(acc[mt][nt][2], acc[mt][nt][3]);
        }
}

// =============== GEMM variant 1: A fp16, W split hi/lo (2 MMA) ===========
#define STG2 24576   // A 8K | Bh 8K | Bl 8K
__global__ __launch_bounds__(256) void gemm_w2(
    const __half* __restrict__ A, const __half* __restrict__ Bh,
    const __half* __restrict__ Bl, float* __restrict__ C, int M, int N, int K)
{
    extern __shared__ __align__(128) char smem[];
    uint32_t sb = smem_to_u32(smem);
    int tid = threadIdx.x, lane = tid & 31, wid = tid >> 5;
    int wm = wid & 3, wn = wid >> 2;
    int bx = blockIdx.x, by = blockIdx.y;
    const int NC = K >> 5;

    float acc[2][8][4];
    #pragma unroll
    for (int i = 0; i < 2; i++)
        #pragma unroll
        for (int j = 0; j < 8; j++)
            #pragma unroll
            for (int q = 0; q < 4; q++) acc[i][j][q] = 0.f;

    #define LOAD_W2(ic, s) do { \
        long kof = (long)(ic) * 32; \
        uint32_t st = sb + (s)*STG2; \
        _Pragma("unroll") \
        for (int j = 0; j < 2; j++) { \
            int u = tid + j*256; int row = u >> 2, kc = u & 3; \
            uint32_t sw = tunit(row, kc); \
            long ao = (long)(by*128 + row)*K + kof + kc*8; \
            long bo = (long)(bx*128 + row)*K + kof + kc*8; \
            CP16(st + sw,          A  + ao); \
            CP16(st + 8192 + sw,   Bh + bo); \
            CP16(st + 16384 + sw,  Bl + bo); \
        } \
        CP_COMMIT(); \
    } while (0)

    LOAD_W2(0, 0);
    LOAD_W2(1, 1);

    int lr = lane & 15, lk = lane >> 4;
    for (int ic = 0; ic < NC; ic++) {
        int s = ic - (ic/3)*3;
        if (ic + 1 < NC) CP_WAIT1(); else CP_WAIT0();
        __syncthreads();
        if (ic + 2 < NC) { int s2 = (ic+2) - ((ic+2)/3)*3; LOAD_W2(ic + 2, s2); }

        uint32_t pA = sb + s*STG2, pBh = pA + 8192, pBl = pA + 16384;
        #pragma unroll
        for (int ks = 0; ks < 2; ks++) {
            uint32_t a[2][4], bh[8][2], bl[8][2];
            #pragma unroll
            for (int mt = 0; mt < 2; mt++)
                ldsm_x4(a[mt], pA + tunit(wm*32 + mt*16 + lr, ks*2 + lk));
            #pragma unroll
            for (int bp = 0; bp < 4; bp++) {
                uint32_t off = tunit(wn*64 + bp*16 + lr, ks*2 + lk);
                uint32_t t[4];
                ldsm_x4(t, pBh + off);
                bh[bp*2][0]=t[0]; bh[bp*2][1]=t[2]; bh[bp*2+1][0]=t[1]; bh[bp*2+1][1]=t[3];
                ldsm_x4(t, pBl + off);
                bl[bp*2][0]=t[0]; bl[bp*2][1]=t[2]; bl[bp*2+1][0]=t[1]; bl[bp*2+1][1]=t[3];
            }
            #pragma unroll
            for (int mt = 0; mt < 2; mt++)
                #pragma unroll
                for (int nt = 0; nt < 8; nt++) {
                    mma16816f(acc[mt][nt], a[mt], bh[nt]);
                    mma16816f(acc[mt][nt], a[mt], bl[nt]);
                }
        }
    }

    #pragma unroll
    for (int mt = 0; mt < 2; mt++)
        #pragma unroll
        for (int nt = 0; nt < 8; nt++) {
            long r = by*128 + wm*32 + mt*16 + (lane >> 2);
            long c = bx*128 + wn*64 + nt*8 + (lane & 3)*2;
            *(float2*)&C[r*N + c]     = make_float2(acc[mt][nt][0], acc[mt][nt][1]);
            *(float2*)&C[(r+8)*N + c] = make_float2(acc[mt][nt][2], acc[mt][nt][3]);
        }
}

// ======================= beta / g projections =============================
__global__ __launch_bounds__(256) void betag_kernel(
    const float* __restrict__ hid, const float* __restrict__ Wb,
    const float* __restrict__ Wa, const float* __restrict__ dtb,
    const float* __restrict__ Alog)
{
    int row = blockIdx.x;
    int tid = threadIdx.x;
    __shared__ float sh[D_];
    __shared__ float red[256];
    *(float4*)&sh[tid*4] = *(const float4*)(hid + (long)row*D_ + tid*4);
    __syncthreads();
    int c  = tid & 31, sg = tid >> 5;
    const float* W = (c < 16) ? Wb : Wa;
    int cc = c & 15, k0 = sg * 128;
    float acc = 0.f;
    #pragma unroll 8
    for (int k = 0; k < 128; k++)
        acc = fmaf(sh[k0 + k], W[(k0 + k)*HV_ + cc], acc);
    red[tid] = acc;
    __syncthreads();
    if (tid < 32) {
        float s = 0.f;
        #pragma unroll
        for (int si = 0; si < 8; si++) s += red[si*32 + c];
        if (c < 16) g_beta[(long)row*HV_ + cc] = 1.f / (1.f + expf(-s));
        else {
            float x  = s + dtb[cc];
            float sp = (x > 20.f) ? x : log1pf(expf(x));
            g_gg[(long)row*HV_ + cc] = -expf(Alog[cc]) * sp;
        }
    }
}

// ===== causal conv + SiLU + split + l2norm; 4 timesteps per block =========
__global__ __launch_bounds__(256) void conv_kernel(const float* __restrict__ convw)
{
    int t0 = blockIdx.x * 4, b = blockIdx.y;
    int tid = threadIdx.x;
    __shared__ float sy[4][CONVD];

    #pragma unroll
    for (int jt = 0; jt < 4; jt++) {
        int t = t0 + jt;
        long row = (long)(b*T_ + t);
        #pragma unroll
        for (int j = 0; j < 8; j++) {
            int c = tid + j*256;
            float4 w = *(const float4*)(convw + c*4);
            float acc = g_mixed[row*MIXW + c] * w.w;
            if (t >= 1) acc = fmaf(g_mixed[(row-1)*MIXW + c], w.z, acc);
            if (t >= 2) acc = fmaf(g_mixed[(row-2)*MIXW + c], w.y, acc);
            if (t >= 3) acc = fmaf(g_mixed[(row-3)*MIXW + c], w.x, acc);
            sy[jt][c] = acc / (1.f + __expf(-acc));
        }
    }
    __syncthreads();

    int wrp = tid >> 5, lane = tid & 31;
    #pragma unroll
    for (int jt = 0; jt < 4; jt++) {
        long row = (long)(b*T_ + t0 + jt);
        {
            float y0 = sy[jt][wrp*64 + lane], y1 = sy[jt][wrp*64 + 32 + lane];
            float ss = y0*y0 + y1*y1;
            #pragma unroll
            for (int off = 16; off; off >>= 1) ss += __shfl_xor_sync(0xffffffffu, ss, off);
            float rs = rsqrtf(ss + EPS_) * 0.125f;
            g_qn[(row*HK_ + wrp)*64 + lane]      = y0 * rs;
            g_qn[(row*HK_ + wrp)*64 + 32 + lane] = y1 * rs;
        }
        {
            float y0 = sy[jt][KDIM_ + wrp*64 + lane], y1 = sy[jt][KDIM_ + wrp*64 + 32 + lane];
            float ss = y0*y0 + y1*y1;
            #pragma unroll
            for (int off = 16; off; off >>= 1) ss += __shfl_xor_sync(0xffffffffu, ss, off);
            float rs = rsqrtf(ss + EPS_);
            g_kn[(row*HK_ + wrp)*64 + lane]      = y0 * rs;
            g_kn[(row*HK_ + wrp)*64 + 32 + lane] = y1 * rs;
        }
        #pragma unroll
        for (int j = 0; j < 4; j++) {
            int c = tid + j*256;
            g_v[row*VDIM_ + c] = sy[jt][1024 + c];
        }
    }
}

// ======= gated delta recurrence: depth-4 prefetch (R7 verbatim) ===========
#define PF 4
__global__ __launch_bounds__(128) void recurrence_kernel()
{
    int w = blockIdx.x*4 + (threadIdx.x >> 5);    // 0..511
    int lane = threadIdx.x & 31;
    int bh = w >> 4, cg = w & 15;
    int b = bh >> 4, h = bh & 15, kh = h >> 1;
    int colIdx = lane >> 3, rseg = lane & 7;
    int col = cg*4 + colIdx;

    const float* kb = g_kn   + ((long)(b*T_)*HK_ + kh)*64 + rseg*8;
    const float* qb = g_qn   + ((long)(b*T_)*HK_ + kh)*64 + rseg*8;
    const float* vb = g_v    + ((long)(b*T_)*HV_ + h)*64 + col;
    const float* gb = g_gg   + (long)(b*T_)*HV_ + h;
    const float* bb = g_beta + (long)(b*T_)*HV_ + h;
    float*       ob = g_o    + ((long)(b*T_)*HV_ + h)*64 + col;
    const long qs = (long)HK_*64, vs = (long)HV_*64, gs = HV_;

    float S[8], kprev[8], dprev = 0.f;
    #pragma unroll
    for (int i = 0; i < 8; i++) { S[i] = 0.f; kprev[i] = 0.f; }

    float4 pk0[PF], pk1[PF], pq0[PF], pq1[PF];
    float  pv[PF], pg[PF], pb[PF];
    #pragma unroll
    for (int j = 0; j < PF; j++) {
        long o = j;
        pk0[j] = *(const float4*)(kb + o*qs);  pk1[j] = *(const float4*)(kb + o*qs + 4);
        pq0[j] = *(const float4*)(qb + o*qs);  pq1[j] = *(const float4*)(qb + o*qs + 4);
        pv[j] = vb[o*vs];  pg[j] = gb[o*gs];  pb[j] = bb[o*gs];
    }

    for (int t0 = 0; t0 < T_; t0 += PF) {
        #pragma unroll
        for (int j = 0; j < PF; j++) {
            int t = t0 + j;
            float4 k0 = pk0[j], k1 = pk1[j], q0 = pq0[j], q1 = pq1[j];
            float vv = pv[j], gv = pg[j], bv = pb[j];
            if (t + PF < T_) {
                long o = (long)(t + PF);
                pk0[j] = *(const float4*)(kb + o*qs);  pk1[j] = *(const float4*)(kb + o*qs + 4);
                pq0[j] = *(const float4*)(qb + o*qs);  pq1[j] = *(const float4*)(qb + o*qs + 4);
                pv[j] = vb[o*vs];  pg[j] = gb[o*gs];  pb[j] = bb[o*gs];
            }

            float eg = __expf(gv);
            float kc[8] = {k0.x,k0.y,k0.z,k0.w,k1.x,k1.y,k1.z,k1.w};
            float qc[8] = {q0.x,q0.y,q0.z,q0.w,q1.x,q1.y,q1.z,q1.w};
            float kva = 0.f, kvb2 = 0.f, oa = 0.f, ob2 = 0.f, qa = 0.f, qb2 = 0.f;
            #pragma unroll
            for (int i = 0; i < 4; i++) {
                S[i] = fmaf(kprev[i], dprev, S[i]) * eg;
                kva = fmaf(kc[i], S[i], kva);
                oa  = fmaf(qc[i], S[i], oa);
                qa  = fmaf(qc[i], kc[i], qa);
                kprev[i] = kc[i];
            }
            #pragma unroll
            for (int i = 4; i < 8; i++) {
                S[i] = fmaf(kprev[i], dprev, S[i]) * eg;
                kvb2 = fmaf(kc[i], S[i], kvb2);
                ob2  = fmaf(qc[i], S[i], ob2);
                qb2  = fmaf(qc[i], kc[i], qb2);
                kprev[i] = kc[i];
            }
            float kvp = kva + kvb2, op = oa + ob2, qkp = qa + qb2;
            #pragma unroll
            for (int off = 1; off < 8; off <<= 1) {
                kvp += __shfl_xor_sync(0xffffffffu, kvp, off);
                op  += __shfl_xor_sync(0xffffffffu, op,  off);
                qkp += __shfl_xor_sync(0xffffffffu, qkp, off);
            }
            float delta = (vv - kvp) * bv;
            if (rseg == 0) ob[(long)t*vs] = fmaf(qkp, delta, op);
            dprev = delta;
        }
    }
}

// ========== gated RMSNorm * silu(z), emits fp16 for GEMM3 =================
__global__ __launch_bounds__(256) void gnorm_kernel(const float* __restrict__ nw)
{
    int t = blockIdx.x, b = blockIdx.y;
    long row = (long)(b*T_ + t);
    int wrp = threadIdx.x >> 5, lane = threadIdx.x & 31;
    #pragma unroll
    for (int hh = wrp; hh < HV_; hh += 8) {
        float o0 = g_o[(row*HV_ + hh)*64 + lane];
        float o1 = g_o[(row*HV_ + hh)*64 + 32 + lane];
        float ss = o0*o0 + o1*o1;
        #pragma unroll
        for (int off = 16; off; off >>= 1) ss += __shfl_xor_sync(0xffffffffu, ss, off);
        float rs = rsqrtf(ss * (1.f/64.f) + EPS_);
        float z0 = g_mixed[row*MIXW + CONVD + hh*64 + lane];
        float z1 = g_mixed[row*MIXW + CONVD + hh*64 + 32 + lane];
        float v0 = o0 * rs * nw[lane]      * (z0 / (1.f + __expf(-z0)));
        float v1 = o1 * rs * nw[lane + 32] * (z1 / (1.f + __expf(-z1)));
        long i0 = row*VDIM_ + hh*64 + lane;
        g_on[i0]      = __float2half(v0);
        g_on[i0 + 32] = __float2half(v1);
    }
}

// ==========================================================================
extern "C" void kernel_launch(void* const* d_in, const int* in_sizes, int n_in,
                              void* d_out, int out_size)
{
    (void)in_sizes; (void)n_in; (void)out_size;
    const float* hid   = (const float*)d_in[0];
    const float* Wqkv  = (const float*)d_in[1];
    const float* Wz    = (const float*)d_in[2];
    const float* Wb    = (const float*)d_in[3];
    const float* Wa    = (const float*)d_in[4];
    const float* dtb   = (const float*)d_in[5];
    const float* Alog  = (const float*)d_in[6];
    const float* convw = (const float*)d_in[7];
    const float* nw    = (const float*)d_in[8];
    const float* Wout  = (const float*)d_in[9];
    float* out = (float*)d_out;

    float *mixed;
    __half *hh, *w1, *woh, *wol, *on;
    cudaGetSymbolAddress((void**)&mixed, g_mixed);
    cudaGetSymbolAddress((void**)&hh,  g_hid);
    cudaGetSymbolAddress((void**)&w1,  g_w1);
    cudaGetSymbolAddress((void**)&woh, g_woh);  cudaGetSymbolAddress((void**)&wol, g_wol);
    cudaGetSymbolAddress((void**)&on,  g_on);

    static int smem_set = 0;
    if (!smem_set) {
        cudaFuncSetAttribute(gemm_h1, cudaFuncAttributeMaxDynamicSharedMemorySize, 3*STG1);
        cudaFuncSetAttribute(gemm_w2, cudaFuncAttributeMaxDynamicSharedMemorySize, 3*STG2);
        smem_set = 1;
    }

    // conversions
    cvt_f2h<<<(NTOK*D_/4 + 255)/256, 256>>>(hid, hh, NTOK*D_/4);
    tconv_f2h<<<dim3(CONVD/32, D_/32), dim3(32,8)>>>(Wqkv, w1, D_, CONVD);
    tconv_f2h<<<dim3(VDIM_/32, D_/32), dim3(32,8)>>>(Wz, w1 + (long)CONVD*D_, D_, VDIM_);
    tconv_f2h2<<<dim3(D_/32, VDIM_/32), dim3(32,8)>>>(Wout, woh, wol, VDIM_, D_);

    // fused GEMM: [mixed | z] = hid @ [Wqkv | Wz]   (single fp16 MMA)
    gemm_h1<<<dim3(MIXW/128, NTOK/128), 256, 3*STG1>>>(hh, w1, mixed, NTOK, MIXW, D_);
    // beta / g
    betag_kernel<<<NTOK, 256>>>(hid, Wb, Wa, dtb, Alog);
    // conv + silu + split + l2norm  (4 timesteps per block)
    conv_kernel<<<dim3(T_/4, B_), 256>>>(convw);
    // recurrence (R7 verbatim)
    recurrence_kernel<<<128, 128>>>();
    // gated RMSNorm -> fp16
    gnorm_kernel<<<dim3(T_, B_), 256>>>(nw);
    // GEMM3: out = on @ Wout  (W compensated, 2 MMA)
    gemm_w2<<<dim3(D_/128, NTOK/128), 256, 3*STG2>>>(on, woh, wol, out, NTOK, D_, VDIM_);
}